// round 11
// baseline (speedup 1.0000x reference)
#include <cuda_runtime.h>
#include <cuda_bf16.h>
#include <cuda_fp16.h>
#include <math.h>
#include <stdint.h>

#define B 8
#define SEQ 2048
#define HID 512
#define HD 64

// ---------------- scratch (device globals; no allocation allowed) ----------------
__device__ __align__(256) uint16_t gQf[B * SEQ * HD];   // fp16 single
__device__ __align__(256) uint16_t gKf[B * SEQ * HD];   // fp16 single
__device__ __align__(256) uint16_t gVf[B * SEQ * HD];   // fp16 single
__device__ __align__(256) uint16_t gWf[192 * HID];      // fp16 W, [region*64+d][k]
__device__ __align__(256) float gC[B * 8 * HD * HD];    // chunk KV states, fp32
__device__ float tQc[SEQ * 32], tQs[SEQ * 32], tKc[SEQ * 32], tKs[SEQ * 32];
__device__ float tDec[4096];   // gamma^|d|, index d+2048

// ---------------- helpers ----------------
__device__ __forceinline__ void mma_f16(float* d, const uint32_t* a, const uint32_t* b) {
    asm volatile(
        "mma.sync.aligned.m16n8k16.row.col.f32.f16.f16.f32 "
        "{%0,%1,%2,%3}, {%4,%5,%6,%7}, {%8,%9}, {%0,%1,%2,%3};"
        : "+f"(d[0]), "+f"(d[1]), "+f"(d[2]), "+f"(d[3])
        : "r"(a[0]), "r"(a[1]), "r"(a[2]), "r"(a[3]), "r"(b[0]), "r"(b[1]));
}
#define LDM_X4(R, a) \
    asm volatile("ldmatrix.sync.aligned.m8n8.x4.shared.b16 {%0,%1,%2,%3}, [%4];" \
                 : "=r"((R)[0]), "=r"((R)[1]), "=r"((R)[2]), "=r"((R)[3]) : "r"(a))
#define LDM_X4T(R, a) \
    asm volatile("ldmatrix.sync.aligned.m8n8.x4.trans.shared.b16 {%0,%1,%2,%3}, [%4];" \
                 : "=r"((R)[0]), "=r"((R)[1]), "=r"((R)[2]), "=r"((R)[3]) : "r"(a))
#define CPA16(dst, src) \
    asm volatile("cp.async.ca.shared.global [%0], [%1], 16;" \
                 :: "r"(dst), "l"(__cvta_generic_to_global(src)))
#define CPA_COMMIT() asm volatile("cp.async.commit_group;")
#define CPA_WAIT1() asm volatile("cp.async.wait_group 1;")
#define CPA_WAIT0() asm volatile("cp.async.wait_group 0;")
__device__ __forceinline__ uint32_t smem_u32(const void* p) {
    uint32_t a;
    asm("{ .reg .u64 t; cvta.to.shared.u64 t, %1; cvt.u32.u64 %0, t; }" : "=r"(a) : "l"(p));
    return a;
}
__device__ __forceinline__ uint32_t packf16(float x0, float x1) {
    __half2 h = __floats2half2_rn(x0, x1);
    return *reinterpret_cast<uint32_t*>(&h);
}
__device__ __forceinline__ uint32_t splitf16(float x0, float x1, uint32_t& lo) {
    __half2 h = __floats2half2_rn(x0, x1);
    float2 hf = __half22float2(h);
    __half2 l = __floats2half2_rn(x0 - hf.x, x1 - hf.y);
    lo = *reinterpret_cast<uint32_t*>(&l);
    return *reinterpret_cast<uint32_t*>(&h);
}

// ---------------- kernel 0: tables + W fp16 ----------------
__global__ void prep_kernel(const float* __restrict__ WQ,
                            const float* __restrict__ WK,
                            const float* __restrict__ WV) {
    int idx = blockIdx.x * blockDim.x + threadIdx.x;
    if (idx < 4096) {
        float d = fabsf((float)(idx - 2048));
        tDec[idx] = exp2f(log2f(0.96875f) * d);
    }
    if (idx < SEQ * 32) {
        int t = idx >> 5;
        int m = idx & 31;
        float sv = (2.0f * (float)m + 0.4f * (float)HD) / (1.4f * (float)HD);
        float p = ((float)t * (1.0f / 512.0f)) * log2f(sv);
        float s = exp2f(p);
        float rs = exp2f(-p);
        float invf = 1.0f / powf(10000.0f, (float)m / 32.0f);
        float sn, cs;
        sincosf((float)t * invf, &sn, &cs);
        tQc[idx] = cs * s;
        tQs[idx] = sn * s;
        tKc[idx] = cs * rs;
        tKs[idx] = sn * rs;
    }
    if (idx < 3 * HID * HD) {
        int region = idx >> 15;
        int k = (idx & 32767) >> 6;
        int d = idx & 63;
        const float* W = (region == 0) ? WQ : ((region == 1) ? WK : WV);
        __half hw = __float2half_rn(W[k * HD + d]);
        gWf[(region * 64 + d) * HID + k] = *reinterpret_cast<uint16_t*>(&hw);
    }
}

// ---------------- kernel 1: QKV projection, fp16 1-term HMMA + xPos (k-chunk 128) ----------------
// 128 CTAs x 512 thr (16 warps 4x4). CTA tile 128x192, warp tile 32x48.
#define PSTRH 136                  // halfs per smem row (272 B)
#define P_WB(s) ((s) * 52224)      // fp16 W stage, 192 x 128 (stride 272B)
#define P_A 104448                 // fp16 X tile, 128 x 128 (stride 272B)
#define P_TOTAL 139264

__global__ __launch_bounds__(512, 1) void proj_kernel(const float* __restrict__ X) {
    extern __shared__ char sm[];
    uint16_t* Ah = (uint16_t*)(sm + P_A);
    uint32_t smb = smem_u32(sm);

    int tid = threadIdx.x;
    int wid = tid >> 5, lane = tid & 31;
    int wm = wid >> 2, wn = wid & 3;
    int g = lane >> 2, tc = lane & 3;

    int arow = lane & 15;
    int acolb = (lane >> 4) * 16;
    int krow = (lane & 7) + ((lane >> 4) << 3);
    int kcolb = ((lane >> 3) & 1) * 16;

    const float* Xb = X + (size_t)blockIdx.x * 128 * HID;

    float acc[2][6][4];
#pragma unroll
    for (int mt = 0; mt < 2; mt++)
#pragma unroll
        for (int nt = 0; nt < 6; nt++)
#pragma unroll
            for (int i = 0; i < 4; i++) acc[mt][nt][i] = 0.0f;

    // X for chunk 0 into registers (128 rows x 128 cols fp32)
    float4 xr[8];
#pragma unroll
    for (int it = 0; it < 8; it++) {
        int e = tid + it * 512;
        int r = e >> 5, c = e & 31;
        xr[it] = *(const float4*)&Xb[r * HID + c * 4];
    }
    // W chunk 0 via cp.async (192 rows x 128 halfs)
#pragma unroll
    for (int it = 0; it < 6; it++) {
        int e = tid + it * 512;
        int r = e >> 4, c = e & 15;
        CPA16(smb + P_WB(0) + r * 272 + c * 16, &gWf[r * HID + c * 8]);
    }
    CPA_COMMIT();

    for (int chunk = 0; chunk < 4; chunk++) {
        int s = chunk & 1;
        int k0n = (chunk + 1) * 128;
        if (chunk < 3) {
#pragma unroll
            for (int it = 0; it < 6; it++) {
                int e = tid + it * 512;
                int r = e >> 4, c = e & 15;
                CPA16(smb + P_WB(s ^ 1) + r * 272 + c * 16, &gWf[r * HID + k0n + c * 8]);
            }
            CPA_COMMIT();
        }
        // convert register X -> Ah (fp16 single)
#pragma unroll
        for (int it = 0; it < 8; it++) {
            int e = tid + it * 512;
            int r = e >> 5, c = e & 31;
            float4 v = xr[it];
            *(uint2*)&Ah[r * PSTRH + 4 * c] =
                make_uint2(packf16(v.x, v.y), packf16(v.z, v.w));
        }
        if (chunk < 3) {
#pragma unroll
            for (int it = 0; it < 8; it++) {
                int e = tid + it * 512;
                int r = e >> 5, c = e & 31;
                xr[it] = *(const float4*)&Xb[r * HID + k0n + c * 4];
            }
        }
        if (chunk < 3) { CPA_WAIT1(); } else { CPA_WAIT0(); }
        __syncthreads();

        uint32_t wbase = smb + P_WB(s);
#pragma unroll
        for (int ks = 0; ks < 8; ks++) {
            uint32_t ah[2][4];
#pragma unroll
            for (int mt = 0; mt < 2; mt++) {
                uint32_t rb = (uint32_t)((wm * 32 + mt * 16 + arow) * 272 + ks * 32 + acolb);
                LDM_X4(ah[mt], smb + P_A + rb);
            }
#pragma unroll
            for (int np = 0; np < 3; np++) {
                int n = wn * 48 + np * 16;
                uint32_t bb = (uint32_t)((n + krow) * 272 + ks * 32 + kcolb);
                uint32_t bf[4];
                LDM_X4(bf, wbase + bb);
#pragma unroll
                for (int mt = 0; mt < 2; mt++) {
                    mma_f16(acc[mt][2 * np], ah[mt], &bf[0]);
                    mma_f16(acc[mt][2 * np + 1], ah[mt], &bf[2]);
                }
            }
        }
        __syncthreads();
    }

    // epilogue: rotary, store Q/K/V fp16 single
#pragma unroll
    for (int mt = 0; mt < 2; mt++) {
#pragma unroll
        for (int half = 0; half < 2; half++) {
            int lrow = wm * 32 + mt * 16 + g + half * 8;
            int grow = blockIdx.x * 128 + lrow;
            int tpos = grow & (SEQ - 1);
#pragma unroll
            for (int nt = 0; nt < 6; nt++) {
                int c = wn * 48 + nt * 8 + 2 * tc;
                float v0 = acc[mt][nt][half * 2];
                float v1 = acc[mt][nt][half * 2 + 1];
                if (c < 64) {
                    int m = c >> 1;
                    float cs = tQc[tpos * 32 + m], sn = tQs[tpos * 32 + m];
                    ((uint32_t*)gQf)[grow * 32 + m] = packf16(v0 * cs - v1 * sn, v1 * cs + v0 * sn);
                } else if (c < 128) {
                    int m = (c - 64) >> 1;
                    float cs = tKc[tpos * 32 + m], sn = tKs[tpos * 32 + m];
                    ((uint32_t*)gKf)[grow * 32 + m] = packf16(v0 * cs - v1 * sn, v1 * cs + v0 * sn);
                } else {
                    int m = (c - 128) >> 1;
                    ((uint32_t*)gVf)[grow * 32 + m] = packf16(v0, v1);
                }
            }
        }
    }
}

// ---------------- kernel 1.5: chunk KV state C_c (fp16 1-term) ----------------
#define SC_K 0
#define SC_V 9216
#define SC_TOTAL 18432

__global__ __launch_bounds__(128) void state_kernel() {
    extern __shared__ char sm[];
    uint32_t smb = smem_u32(sm);
    int c = blockIdx.x, b = blockIdx.y;
    int tid = threadIdx.x;
    int wid = tid >> 5, lane = tid & 31;
    int g = lane >> 2, tc = lane & 3;

    int arow = lane & 15;
    int acolb = (lane >> 4) * 16;
    int krow = (lane & 7) + ((lane >> 4) << 3);
    int kcolb = ((lane >> 3) & 1) * 16;

    float acc[8][4];
#pragma unroll
    for (int nd = 0; nd < 8; nd++)
#pragma unroll
        for (int i = 0; i < 4; i++) acc[nd][i] = 0.0f;

    for (int jt = 0; jt < 4; jt++) {
        __syncthreads();
        int jb = b * SEQ + c * 256 + jt * 64;
#pragma unroll
        for (int it = 0; it < 4; it++) {
            int e = tid + it * 128;
            int r = e >> 3, cc = e & 7;
            *(float4*)(sm + SC_K + r * 144 + cc * 16) = *(const float4*)&gKf[(size_t)(jb + r) * HD + cc * 8];
        }
#pragma unroll
        for (int it = 0; it < 16; it++) {
            int p = tid + it * 128;
            int r = p >> 5, vp = p & 31;
            uint32_t u = ((const uint32_t*)gVf)[(size_t)(jb + r) * 32 + vp];
            __half2 hv = *reinterpret_cast<__half2*>(&u);
            float2 f = __half22float2(hv);
            float w = tDec[2304 - (jt * 64 + r)];
            *(uint32_t*)(sm + SC_V + r * 144 + vp * 4) = packf16(w * f.x, w * f.y);
        }
        __syncthreads();

#pragma unroll
        for (int ks = 0; ks < 4; ks++) {
            uint32_t ab = (uint32_t)((ks * 16 + krow) * 144 + wid * 32 + kcolb);
            uint32_t ah[4];
            LDM_X4T(ah, smb + SC_K + ab);
#pragma unroll
            for (int ndp = 0; ndp < 4; ndp++) {
                uint32_t vb = (uint32_t)((ks * 16 + arow) * 144 + ndp * 32 + acolb);
                uint32_t vh[4];
                LDM_X4T(vh, smb + SC_V + vb);
                mma_f16(acc[2 * ndp], ah, &vh[0]);
                mma_f16(acc[2 * ndp + 1], ah, &vh[2]);
            }
        }
    }

    float* Cb = gC + ((size_t)(b * 8 + c)) * 4096;
#pragma unroll
    for (int nd = 0; nd < 8; nd++) {
        int v = nd * 8 + 2 * tc;
        int d0 = wid * 16 + g;
        *(float2*)&Cb[d0 * 64 + v] = make_float2(acc[nd][0], acc[nd][1]);
        *(float2*)&Cb[(d0 + 8) * 64 + v] = make_float2(acc[nd][2], acc[nd][3]);
    }
}

// ---------------- kernel 2: retention attention (fp16 1-term, whole-chunk staging) ----------------
// grid (16, 8) x 256 thr (8 warps). Warp = 16 q-rows x full 64. K/V for all 4
// tiles loaded in ONE cp.async batch; no barriers between tiles.
#define A_Q 0            // 128 x 144B = 18432
#define A_MH 18432       // 64 x 144B
#define A_ML 27648
#define A_K 36864        // 256 x 144B = 36864
#define A_V 73728
#define A_DEC 110592     // 511 floats
#define A_TOTAL 112640

__global__ __launch_bounds__(256) void attn_kernel(float* __restrict__ out) {
    extern __shared__ char sm[];
    uint16_t* Qs = (uint16_t*)(sm + A_Q);
    float* sDec = (float*)(sm + A_DEC);
    uint32_t smb = smem_u32(sm);

    int qtp = blockIdx.x, b = blockIdx.y;
    int tid = threadIdx.x;
    int wid = tid >> 5, lane = tid & 31;
    int qsub = wid >> 2, wq = wid & 3;
    int g = lane >> 2, tc = lane & 3;
    int q0 = qtp * 128;
    int gb = b * SEQ + q0;
    int chunk = qtp >> 1;

    int arow = lane & 15;
    int acolb = (lane >> 4) * 16;
    int krow = (lane & 7) + ((lane >> 4) << 3);
    int kcolb = ((lane >> 3) & 1) * 16;

    // ---- one-shot K/V staging: whole chunk (256 rows) ----
    {
        int kb0 = b * SEQ + chunk * 256;
#pragma unroll
        for (int it = 0; it < 8; it++) {
            int e = tid + it * 256;
            int r = e >> 3, c = e & 7;
            uint32_t off = (uint32_t)(r * 144 + c * 16);
            CPA16(smb + A_K + off, &gKf[(size_t)(kb0 + r) * HD + c * 8]);
            CPA16(smb + A_V + off, &gVf[(size_t)(kb0 + r) * HD + c * 8]);
        }
        CPA_COMMIT();
    }

    // Q (128 rows fp16), decay window, state M
#pragma unroll
    for (int it = 0; it < 4; it++) {
        int e = tid + it * 256;
        int r = e >> 3, c = e & 7;
        *(float4*)&Qs[r * 72 + c * 8] = *(const float4*)&gQf[(size_t)(gb + r) * HD + c * 8];
    }
    for (int d = tid; d < 511; d += 256) sDec[d] = tDec[d + 1793];
    if (chunk >= 1) {
        const float2* C1 = (const float2*)(gC + ((size_t)(b * 8 + chunk - 1)) * 4096);
        const float2* C2 = (chunk >= 2) ? (const float2*)(gC + ((size_t)(b * 8 + chunk - 2)) * 4096) : (const float2*)0;
        const float G256 = 2.952517e-4f;   // gamma^256
#pragma unroll
        for (int it = 0; it < 8; it++) {
            int p = tid + it * 256;
            int d = p >> 5, vp = p & 31;
            float2 v = C1[p];
            if (C2) {
                float2 w = C2[p];
                v.x += G256 * w.x;
                v.y += G256 * w.y;
            }
            uint32_t lo;
            uint32_t hi = splitf16(v.x, v.y, lo);
            *(uint32_t*)(sm + A_MH + d * 144 + vp * 4) = hi;
            *(uint32_t*)(sm + A_ML + d * 144 + vp * 4) = lo;
        }
    }
    CPA_WAIT0();
    __syncthreads();

    // Q fragments
    uint32_t qh[4][4];
#pragma unroll
    for (int ks = 0; ks < 4; ks++) {
        uint32_t rb = (uint32_t)((qsub * 64 + wq * 16 + arow) * 144 + ks * 32 + acolb);
        LDM_X4(qh[ks], smb + A_Q + rb);
    }

    float oa[8][4];
#pragma unroll
    for (int nd = 0; nd < 8; nd++)
#pragma unroll
        for (int i = 0; i < 4; i++) oa[nd][i] = 0.0f;

    int i0 = q0 + qsub * 64 + wq * 16 + g;

    // ---- state apply: O += gamma^(i-c0) * Q @ (Mh+Ml) ----
    if (chunk >= 1) {
        float T[8][4];
#pragma unroll
        for (int nd = 0; nd < 8; nd++)
#pragma unroll
            for (int i = 0; i < 4; i++) T[nd][i] = 0.0f;
#pragma unroll
        for (int ks = 0; ks < 4; ks++) {
#pragma unroll
            for (int ndp = 0; ndp < 4; ndp++) {
                uint32_t vb = (uint32_t)((ks * 16 + arow) * 144 + ndp * 32 + acolb);
                uint32_t mh[4], ml[4];
                LDM_X4T(mh, smb + A_MH + vb);
                LDM_X4T(ml, smb + A_ML + vb);
                mma_f16(T[2 * ndp], qh[ks], &mh[0]);
                mma_f16(T[2 * ndp], qh[ks], &ml[0]);
                mma_f16(T[2 * ndp + 1], qh[ks], &mh[2]);
                mma_f16(T[2 * ndp + 1], qh[ks], &ml[2]);
            }
        }
        int c0 = chunk * 256;
        float sc0 = sDec[i0 - c0 + 255];
        float sc1 = sDec[i0 + 8 - c0 + 255];
#pragma unroll
        for (int nd = 0; nd < 8; nd++) {
            oa[nd][0] += sc0 * T[nd][0];
            oa[nd][1] += sc0 * T[nd][1];
            oa[nd][2] += sc1 * T[nd][2];
            oa[nd][3] += sc1 * T[nd][3];
        }
    }

    // ---- 4 intra-chunk tiles, no barriers ----
#pragma unroll
    for (int i = 0; i < 4; i++) {
        int kt = chunk * 4 + i;
        uint32_t kB = smb + A_K + (uint32_t)(i * 64 * 144);
        uint32_t vB = smb + A_V + (uint32_t)(i * 64 * 144);

        float sreg[8][4];
#pragma unroll
        for (int nt = 0; nt < 8; nt++)
#pragma unroll
            for (int ii = 0; ii < 4; ii++) sreg[nt][ii] = 0.0f;

        // S = Q K^T (1-term)
#pragma unroll
        for (int ks = 0; ks < 4; ks++) {
#pragma unroll
            for (int np = 0; np < 4; np++) {
                uint32_t bb = (uint32_t)((np * 16 + krow) * 144 + ks * 32 + kcolb);
                uint32_t kh[4];
                LDM_X4(kh, kB + bb);
                mma_f16(sreg[2 * np], qh[ks], &kh[0]);
                mma_f16(sreg[2 * np + 1], qh[ks], &kh[2]);
            }
        }
        // decay
#pragma unroll
        for (int nt = 0; nt < 8; nt++) {
            int base = i0 - (kt * 64 + nt * 8 + 2 * tc) + 255;
            sreg[nt][0] *= sDec[base];
            sreg[nt][1] *= sDec[base - 1];
            sreg[nt][2] *= sDec[base + 8];
            sreg[nt][3] *= sDec[base + 7];
        }
        // O += S V (1-term)
#pragma unroll
        for (int ks2 = 0; ks2 < 4; ks2++) {
            float* s0 = sreg[2 * ks2];
            float* s1 = sreg[2 * ks2 + 1];
            uint32_t ah[4];
            ah[0] = packf16(s0[0], s0[1]);
            ah[1] = packf16(s0[2], s0[3]);
            ah[2] = packf16(s1[0], s1[1]);
            ah[3] = packf16(s1[2], s1[3]);
#pragma unroll
            for (int ndp = 0; ndp < 4; ndp++) {
                uint32_t vb = (uint32_t)((ks2 * 16 + arow) * 144 + ndp * 32 + acolb);
                uint32_t vh[4];
                LDM_X4T(vh, vB + vb);
                mma_f16(oa[2 * ndp], ah, &vh[0]);
                mma_f16(oa[2 * ndp + 1], ah, &vh[2]);
            }
        }
    }

    // store O
#pragma unroll
    for (int nd = 0; nd < 8; nd++) {
        int c = nd * 8 + 2 * tc;
        int r0 = qsub * 64 + wq * 16 + g;
        *(float2*)&out[(size_t)(gb + r0) * HD + c] = make_float2(oa[nd][0], oa[nd][1]);
        *(float2*)&out[(size_t)(gb + r0 + 8) * HD + c] = make_float2(oa[nd][2], oa[nd][3]);
    }
}

// ---------------- launch ----------------
extern "C" void kernel_launch(void* const* d_in, const int* in_sizes, int n_in,
                              void* d_out, int out_size) {
    const float* X  = (const float*)d_in[0];
    const float* WQ = (const float*)d_in[1];
    const float* WK = (const float*)d_in[2];
    const float* WV = (const float*)d_in[3];
    float* out = (float*)d_out;

    prep_kernel<<<384, 256>>>(WQ, WK, WV);

    cudaFuncSetAttribute(proj_kernel, cudaFuncAttributeMaxDynamicSharedMemorySize, P_TOTAL);
    proj_kernel<<<128, 512, P_TOTAL>>>(X);

    cudaFuncSetAttribute(state_kernel, cudaFuncAttributeMaxDynamicSharedMemorySize, SC_TOTAL);
    state_kernel<<<dim3(7, B), 128, SC_TOTAL>>>();

    cudaFuncSetAttribute(attn_kernel, cudaFuncAttributeMaxDynamicSharedMemorySize, A_TOTAL);
    attn_kernel<<<dim3(16, B), 256, A_TOTAL>>>(out);
}

// round 12
// speedup vs baseline: 1.2955x; 1.2955x over previous
#include <cuda_runtime.h>
#include <cuda_bf16.h>
#include <cuda_fp16.h>
#include <math.h>
#include <stdint.h>

#define B 8
#define SEQ 2048
#define HID 512
#define HD 64

// ---------------- scratch (device globals; no allocation allowed) ----------------
__device__ __align__(256) uint16_t gQh[B * SEQ * HD], gQl[B * SEQ * HD];  // fp16 hi/lo
__device__ __align__(256) uint16_t gKf[B * SEQ * HD];                     // fp16 single
__device__ __align__(256) uint16_t gVf[B * SEQ * HD];                     // fp16 single
__device__ __align__(256) uint16_t gWf[192 * HID];     // fp16 W, [region*64+d][k]
__device__ __align__(256) float gC[B * 8 * HD * HD];   // chunk KV states, fp32
__device__ float tQc[SEQ * 32], tQs[SEQ * 32], tKc[SEQ * 32], tKs[SEQ * 32];
__device__ float tDec[4096];   // gamma^|d|, index d+2048

// ---------------- helpers ----------------
__device__ __forceinline__ void mma_f16(float* d, const uint32_t* a, const uint32_t* b) {
    asm volatile(
        "mma.sync.aligned.m16n8k16.row.col.f32.f16.f16.f32 "
        "{%0,%1,%2,%3}, {%4,%5,%6,%7}, {%8,%9}, {%0,%1,%2,%3};"
        : "+f"(d[0]), "+f"(d[1]), "+f"(d[2]), "+f"(d[3])
        : "r"(a[0]), "r"(a[1]), "r"(a[2]), "r"(a[3]), "r"(b[0]), "r"(b[1]));
}
#define LDM_X4(R, a) \
    asm volatile("ldmatrix.sync.aligned.m8n8.x4.shared.b16 {%0,%1,%2,%3}, [%4];" \
                 : "=r"((R)[0]), "=r"((R)[1]), "=r"((R)[2]), "=r"((R)[3]) : "r"(a))
#define LDM_X4T(R, a) \
    asm volatile("ldmatrix.sync.aligned.m8n8.x4.trans.shared.b16 {%0,%1,%2,%3}, [%4];" \
                 : "=r"((R)[0]), "=r"((R)[1]), "=r"((R)[2]), "=r"((R)[3]) : "r"(a))
#define CPA16(dst, src) \
    asm volatile("cp.async.ca.shared.global [%0], [%1], 16;" \
                 :: "r"(dst), "l"(__cvta_generic_to_global(src)))
#define CPA_COMMIT() asm volatile("cp.async.commit_group;")
#define CPA_WAIT1() asm volatile("cp.async.wait_group 1;")
#define CPA_WAIT0() asm volatile("cp.async.wait_group 0;")
__device__ __forceinline__ uint32_t smem_u32(const void* p) {
    uint32_t a;
    asm("{ .reg .u64 t; cvta.to.shared.u64 t, %1; cvt.u32.u64 %0, t; }" : "=r"(a) : "l"(p));
    return a;
}
__device__ __forceinline__ uint32_t packf16(float x0, float x1) {
    __half2 h = __floats2half2_rn(x0, x1);
    return *reinterpret_cast<uint32_t*>(&h);
}
__device__ __forceinline__ uint32_t splitf16(float x0, float x1, uint32_t& lo) {
    __half2 h = __floats2half2_rn(x0, x1);
    float2 hf = __half22float2(h);
    __half2 l = __floats2half2_rn(x0 - hf.x, x1 - hf.y);
    lo = *reinterpret_cast<uint32_t*>(&l);
    return *reinterpret_cast<uint32_t*>(&h);
}

// ---------------- kernel 0: tables + W fp16 ----------------
__global__ void prep_kernel(const float* __restrict__ WQ,
                            const float* __restrict__ WK,
                            const float* __restrict__ WV) {
    int idx = blockIdx.x * blockDim.x + threadIdx.x;
    if (idx < 4096) {
        float d = fabsf((float)(idx - 2048));
        tDec[idx] = exp2f(log2f(0.96875f) * d);
    }
    if (idx < SEQ * 32) {
        int t = idx >> 5;
        int m = idx & 31;
        float sv = (2.0f * (float)m + 0.4f * (float)HD) / (1.4f * (float)HD);
        float p = ((float)t * (1.0f / 512.0f)) * log2f(sv);
        float s = exp2f(p);
        float rs = exp2f(-p);
        float invf = 1.0f / powf(10000.0f, (float)m / 32.0f);
        float sn, cs;
        sincosf((float)t * invf, &sn, &cs);
        tQc[idx] = cs * s;
        tQs[idx] = sn * s;
        tKc[idx] = cs * rs;
        tKs[idx] = sn * rs;
    }
    if (idx < 3 * HID * HD) {
        int region = idx >> 15;
        int k = (idx & 32767) >> 6;
        int d = idx & 63;
        const float* W = (region == 0) ? WQ : ((region == 1) ? WK : WV);
        __half hw = __float2half_rn(W[k * HD + d]);
        gWf[(region * 64 + d) * HID + k] = *reinterpret_cast<uint16_t*>(&hw);
    }
}

// ---------------- kernel 1: QKV projection, fp16 1-term HMMA + xPos ----------------
// 256 CTAs x 256 thr (8 warps 2x4). CTA tile 64x192, warp tile 32x48.
// 2 CTAs/SM -> cross-CTA overlap of barrier/convert phases with mma.
#define PSTR 72
#define P_WB(s) ((s) * 27648)     // fp16 W stage, 192 x 64 (stride 144B)
#define P_A 55296                 // fp16 X tile, 64 x 64 (stride 144B)
#define P_TOTAL 64512

__global__ __launch_bounds__(256, 2) void proj_kernel(const float* __restrict__ X) {
    extern __shared__ char sm[];
    uint16_t* Ah = (uint16_t*)(sm + P_A);
    uint32_t smb = smem_u32(sm);

    int tid = threadIdx.x;
    int wid = tid >> 5, lane = tid & 31;
    int wm = wid >> 2, wn = wid & 3;
    int g = lane >> 2, tc = lane & 3;

    int arow = lane & 15;
    int acolb = (lane >> 4) * 16;
    int krow = (lane & 7) + ((lane >> 4) << 3);
    int kcolb = ((lane >> 3) & 1) * 16;

    const float* Xb = X + (size_t)blockIdx.x * 64 * HID;

    float acc[2][6][4];
#pragma unroll
    for (int mt = 0; mt < 2; mt++)
#pragma unroll
        for (int nt = 0; nt < 6; nt++)
#pragma unroll
            for (int i = 0; i < 4; i++) acc[mt][nt][i] = 0.0f;

    // X for chunk 0 into registers (64 rows x 64 cols fp32 = 1024 float4 / 256 thr)
    float4 xr[4];
#pragma unroll
    for (int it = 0; it < 4; it++) {
        int e = tid + it * 256;
        int r = e >> 4, c = e & 15;
        xr[it] = *(const float4*)&Xb[r * HID + c * 4];
    }
    // W chunk 0 via cp.async (192 rows x 64 halfs = 1536 x 16B / 256 thr)
#pragma unroll
    for (int it = 0; it < 6; it++) {
        int e = tid + it * 256;
        int r = e >> 3, c = e & 7;
        CPA16(smb + P_WB(0) + r * 144 + c * 16, &gWf[r * HID + c * 8]);
    }
    CPA_COMMIT();

    for (int chunk = 0; chunk < 8; chunk++) {
        int s = chunk & 1;
        int k0n = (chunk + 1) * 64;
        if (chunk < 7) {
#pragma unroll
            for (int it = 0; it < 6; it++) {
                int e = tid + it * 256;
                int r = e >> 3, c = e & 7;
                CPA16(smb + P_WB(s ^ 1) + r * 144 + c * 16, &gWf[r * HID + k0n + c * 8]);
            }
            CPA_COMMIT();
        }
        // convert register X -> Ah (fp16 single)
#pragma unroll
        for (int it = 0; it < 4; it++) {
            int e = tid + it * 256;
            int r = e >> 4, c = e & 15;
            float4 v = xr[it];
            *(uint2*)&Ah[r * PSTR + 4 * c] =
                make_uint2(packf16(v.x, v.y), packf16(v.z, v.w));
        }
        if (chunk < 7) {
#pragma unroll
            for (int it = 0; it < 4; it++) {
                int e = tid + it * 256;
                int r = e >> 4, c = e & 15;
                xr[it] = *(const float4*)&Xb[r * HID + k0n + c * 4];
            }
        }
        if (chunk < 7) { CPA_WAIT1(); } else { CPA_WAIT0(); }
        __syncthreads();

        uint32_t wbase = smb + P_WB(s);
#pragma unroll
        for (int ks = 0; ks < 4; ks++) {
            uint32_t ah[2][4];
#pragma unroll
            for (int mt = 0; mt < 2; mt++) {
                uint32_t rb = (uint32_t)((wm * 32 + mt * 16 + arow) * (PSTR * 2) + ks * 32 + acolb);
                LDM_X4(ah[mt], smb + P_A + rb);
            }
#pragma unroll
            for (int np = 0; np < 3; np++) {
                int n = wn * 48 + np * 16;
                uint32_t bb = (uint32_t)((n + krow) * (PSTR * 2) + ks * 32 + kcolb);
                uint32_t bf[4];
                LDM_X4(bf, wbase + bb);
#pragma unroll
                for (int mt = 0; mt < 2; mt++) {
                    mma_f16(acc[mt][2 * np], ah[mt], &bf[0]);
                    mma_f16(acc[mt][2 * np + 1], ah[mt], &bf[2]);
                }
            }
        }
        __syncthreads();
    }

    // epilogue: rotary, then Q -> fp16 hi/lo, K/V -> fp16 single
#pragma unroll
    for (int mt = 0; mt < 2; mt++) {
#pragma unroll
        for (int half = 0; half < 2; half++) {
            int lrow = wm * 32 + mt * 16 + g + half * 8;
            int grow = blockIdx.x * 64 + lrow;
            int tpos = grow & (SEQ - 1);
#pragma unroll
            for (int nt = 0; nt < 6; nt++) {
                int c = wn * 48 + nt * 8 + 2 * tc;
                float v0 = acc[mt][nt][half * 2];
                float v1 = acc[mt][nt][half * 2 + 1];
                if (c < 64) {
                    int m = c >> 1;
                    float cs = tQc[tpos * 32 + m], sn = tQs[tpos * 32 + m];
                    float o0 = v0 * cs - v1 * sn;
                    float o1 = v1 * cs + v0 * sn;
                    uint32_t lo;
                    uint32_t hi = splitf16(o0, o1, lo);
                    ((uint32_t*)gQh)[grow * 32 + m] = hi;
                    ((uint32_t*)gQl)[grow * 32 + m] = lo;
                } else if (c < 128) {
                    int m = (c - 64) >> 1;
                    float cs = tKc[tpos * 32 + m], sn = tKs[tpos * 32 + m];
                    float o0 = v0 * cs - v1 * sn;
                    float o1 = v1 * cs + v0 * sn;
                    ((uint32_t*)gKf)[grow * 32 + m] = packf16(o0, o1);
                } else {
                    int m = (c - 128) >> 1;
                    ((uint32_t*)gVf)[grow * 32 + m] = packf16(v0, v1);
                }
            }
        }
    }
}

// ---------------- kernel 1.5: chunk KV state C_c (fp16 1-term) ----------------
#define SC_K 0
#define SC_V 9216
#define SC_TOTAL 18432

__global__ __launch_bounds__(128) void state_kernel() {
    extern __shared__ char sm[];
    uint32_t smb = smem_u32(sm);
    int c = blockIdx.x, b = blockIdx.y;
    int tid = threadIdx.x;
    int wid = tid >> 5, lane = tid & 31;
    int g = lane >> 2, tc = lane & 3;

    int arow = lane & 15;
    int acolb = (lane >> 4) * 16;
    int krow = (lane & 7) + ((lane >> 4) << 3);
    int kcolb = ((lane >> 3) & 1) * 16;

    float acc[8][4];
#pragma unroll
    for (int nd = 0; nd < 8; nd++)
#pragma unroll
        for (int i = 0; i < 4; i++) acc[nd][i] = 0.0f;

    for (int jt = 0; jt < 4; jt++) {
        __syncthreads();
        int jb = b * SEQ + c * 256 + jt * 64;
#pragma unroll
        for (int it = 0; it < 4; it++) {
            int e = tid + it * 128;
            int r = e >> 3, cc = e & 7;
            *(float4*)(sm + SC_K + r * 144 + cc * 16) = *(const float4*)&gKf[(size_t)(jb + r) * HD + cc * 8];
        }
#pragma unroll
        for (int it = 0; it < 16; it++) {
            int p = tid + it * 128;
            int r = p >> 5, vp = p & 31;
            uint32_t u = ((const uint32_t*)gVf)[(size_t)(jb + r) * 32 + vp];
            __half2 hv = *reinterpret_cast<__half2*>(&u);
            float2 f = __half22float2(hv);
            float w = tDec[2304 - (jt * 64 + r)];
            *(uint32_t*)(sm + SC_V + r * 144 + vp * 4) = packf16(w * f.x, w * f.y);
        }
        __syncthreads();

#pragma unroll
        for (int ks = 0; ks < 4; ks++) {
            uint32_t ab = (uint32_t)((ks * 16 + krow) * 144 + wid * 32 + kcolb);
            uint32_t ah[4];
            LDM_X4T(ah, smb + SC_K + ab);
#pragma unroll
            for (int ndp = 0; ndp < 4; ndp++) {
                uint32_t vb = (uint32_t)((ks * 16 + arow) * 144 + ndp * 32 + acolb);
                uint32_t vh[4];
                LDM_X4T(vh, smb + SC_V + vb);
                mma_f16(acc[2 * ndp], ah, &vh[0]);
                mma_f16(acc[2 * ndp + 1], ah, &vh[2]);
            }
        }
    }

    float* Cb = gC + ((size_t)(b * 8 + c)) * 4096;
#pragma unroll
    for (int nd = 0; nd < 8; nd++) {
        int v = nd * 8 + 2 * tc;
        int d0 = wid * 16 + g;
        *(float2*)&Cb[d0 * 64 + v] = make_float2(acc[nd][0], acc[nd][1]);
        *(float2*)&Cb[(d0 + 8) * 64 + v] = make_float2(acc[nd][2], acc[nd][3]);
    }
}

// ---------------- kernel 2: retention attention (fp16, 128-row CTA, pipelined) ----------------
// grid (16, 8) x 256 thr (8 warps). Warp = 16 q-rows x full 64.
#define ASTR 72
#define A_QH 0
#define A_QL 18432
#define A_MH 36864
#define A_ML 46080
#define A_ST 55296
#define A_STSZ 18432
// within stage: K +0, V +9216
#define A_DEC (A_ST + 2 * A_STSZ)            // 92160: decay window 511 floats
#define A_TOTAL (A_DEC + 2048)               // 94208

__device__ __forceinline__ void attn_prefetch(uint32_t smb, int st, int kb, int tid) {
    uint32_t base = smb + A_ST + st * A_STSZ;
#pragma unroll
    for (int it = 0; it < 2; it++) {
        int e = tid + it * 256;
        int r = e >> 3, c = e & 7;
        uint32_t off = (uint32_t)(r * 144 + c * 16);
        CPA16(base + off, &gKf[(size_t)(kb + r) * HD + c * 8]);
        CPA16(base + 9216 + off, &gVf[(size_t)(kb + r) * HD + c * 8]);
    }
}

__global__ __launch_bounds__(256) void attn_kernel(float* __restrict__ out) {
    extern __shared__ char sm[];
    uint16_t* Qh = (uint16_t*)(sm + A_QH);
    uint16_t* Ql = (uint16_t*)(sm + A_QL);
    float* sDec = (float*)(sm + A_DEC);
    uint32_t smb = smem_u32(sm);

    int qtp = blockIdx.x, b = blockIdx.y;
    int tid = threadIdx.x;
    int wid = tid >> 5, lane = tid & 31;
    int qsub = wid >> 2, wq = wid & 3;
    int g = lane >> 2, tc = lane & 3;
    int q0 = qtp * 128;
    int gb = b * SEQ + q0;
    int chunk = qtp >> 1;
    int c4t = chunk * 4;
    int qt_w = qtp * 2 + qsub;

    int arow = lane & 15;
    int acolb = (lane >> 4) * 16;
    int krow = (lane & 7) + ((lane >> 4) << 3);
    int kcolb = ((lane >> 3) & 1) * 16;

    attn_prefetch(smb, 0, b * SEQ + c4t * 64, tid);
    CPA_COMMIT();

    // load Q (128 rows, fp16 hi/lo), decay window, state M
#pragma unroll
    for (int it = 0; it < 4; it++) {
        int e = tid + it * 256;
        int r = e >> 3, c = e & 7;
        *(float4*)&Qh[r * ASTR + c * 8] = *(const float4*)&gQh[(gb + r) * HD + c * 8];
        *(float4*)&Ql[r * ASTR + c * 8] = *(const float4*)&gQl[(gb + r) * HD + c * 8];
    }
    for (int d = tid; d < 511; d += 256) sDec[d] = tDec[d + 1793];
    if (chunk >= 1) {
        const float2* C1 = (const float2*)(gC + ((size_t)(b * 8 + chunk - 1)) * 4096);
        const float2* C2 = (chunk >= 2) ? (const float2*)(gC + ((size_t)(b * 8 + chunk - 2)) * 4096) : (const float2*)0;
        const float G256 = 2.952517e-4f;   // gamma^256
#pragma unroll
        for (int it = 0; it < 8; it++) {
            int p = tid + it * 256;
            int d = p >> 5, vp = p & 31;
            float2 v = C1[p];
            if (C2) {
                float2 w = C2[p];
                v.x += G256 * w.x;
                v.y += G256 * w.y;
            }
            uint32_t lo;
            uint32_t hi = splitf16(v.x, v.y, lo);
            *(uint32_t*)(sm + A_MH + d * 144 + vp * 4) = hi;
            *(uint32_t*)(sm + A_ML + d * 144 + vp * 4) = lo;
        }
    }
    __syncthreads();

    uint32_t qh[4][4], ql[4][4];
#pragma unroll
    for (int ks = 0; ks < 4; ks++) {
        uint32_t rb = (uint32_t)((qsub * 64 + wq * 16 + arow) * (ASTR * 2) + ks * 32 + acolb);
        LDM_X4(qh[ks], smb + A_QH + rb);
        LDM_X4(ql[ks], smb + A_QL + rb);
    }

    float oa[8][4];
#pragma unroll
    for (int nd = 0; nd < 8; nd++)
#pragma unroll
        for (int i = 0; i < 4; i++) oa[nd][i] = 0.0f;

    int i0 = q0 + qsub * 64 + wq * 16 + g;

    // ---- state apply: O += gamma^(i-c0) * Q @ M (3-term fp16) ----
    if (chunk >= 1) {
        float T[8][4];
#pragma unroll
        for (int nd = 0; nd < 8; nd++)
#pragma unroll
            for (int i = 0; i < 4; i++) T[nd][i] = 0.0f;
#pragma unroll
        for (int ks = 0; ks < 4; ks++) {
#pragma unroll
            for (int ndp = 0; ndp < 4; ndp++) {
                uint32_t vb = (uint32_t)((ks * 16 + arow) * 144 + ndp * 32 + acolb);
                uint32_t mh[4], ml[4];
                LDM_X4T(mh, smb + A_MH + vb);
                LDM_X4T(ml, smb + A_ML + vb);
                mma_f16(T[2 * ndp], qh[ks], &mh[0]);
                mma_f16(T[2 * ndp], qh[ks], &ml[0]);
                mma_f16(T[2 * ndp], ql[ks], &mh[0]);
                mma_f16(T[2 * ndp + 1], qh[ks], &mh[2]);
                mma_f16(T[2 * ndp + 1], qh[ks], &ml[2]);
                mma_f16(T[2 * ndp + 1], ql[ks], &mh[2]);
            }
        }
        int c0 = chunk * 256;
        float sc0 = sDec[i0 - c0 + 255];
        float sc1 = sDec[i0 + 8 - c0 + 255];
#pragma unroll
        for (int nd = 0; nd < 8; nd++) {
            oa[nd][0] += sc0 * T[nd][0];
            oa[nd][1] += sc0 * T[nd][1];
            oa[nd][2] += sc1 * T[nd][2];
            oa[nd][3] += sc1 * T[nd][3];
        }
    }

    // ---- 4 intra-chunk tiles ----
    for (int i = 0; i < 4; i++) {
        int kt = c4t + i;
        int s = i & 1;
        int dd = qt_w - kt;
        bool nr = (dd <= 2) && (dd >= -2);
        if (i < 3) {
            attn_prefetch(smb, s ^ 1, b * SEQ + (kt + 1) * 64, tid);
            CPA_COMMIT();
            CPA_WAIT1();
        } else {
            CPA_WAIT0();
        }
        __syncthreads();

        uint32_t kB = smb + A_ST + s * A_STSZ;
        uint32_t vB = kB + 9216;

        float sreg[8][4];
#pragma unroll
        for (int nt = 0; nt < 8; nt++)
#pragma unroll
            for (int ii = 0; ii < 4; ii++) sreg[nt][ii] = 0.0f;

        if (nr) {
            // ---- S = (Qh+Ql) K ----
#pragma unroll
            for (int ks = 0; ks < 4; ks++) {
#pragma unroll
                for (int np = 0; np < 4; np++) {
                    uint32_t bb = (uint32_t)((np * 16 + krow) * (ASTR * 2) + ks * 32 + kcolb);
                    uint32_t kh[4];
                    LDM_X4(kh, kB + bb);
                    mma_f16(sreg[2 * np], qh[ks], &kh[0]);
                    mma_f16(sreg[2 * np], ql[ks], &kh[0]);
                    mma_f16(sreg[2 * np + 1], qh[ks], &kh[2]);
                    mma_f16(sreg[2 * np + 1], ql[ks], &kh[2]);
                }
            }
#pragma unroll
            for (int nt = 0; nt < 8; nt++) {
                int base = i0 - (kt * 64 + nt * 8 + 2 * tc) + 255;
                sreg[nt][0] *= sDec[base];
                sreg[nt][1] *= sDec[base - 1];
                sreg[nt][2] *= sDec[base + 8];
                sreg[nt][3] *= sDec[base + 7];
            }
            // ---- O += (Sh+Sl) V ----
#pragma unroll
            for (int ks2 = 0; ks2 < 4; ks2++) {
                float* s0 = sreg[2 * ks2];
                float* s1 = sreg[2 * ks2 + 1];
                uint32_t ah[4], al[4];
                ah[0] = splitf16(s0[0], s0[1], al[0]);
                ah[1] = splitf16(s0[2], s0[3], al[1]);
                ah[2] = splitf16(s1[0], s1[1], al[2]);
                ah[3] = splitf16(s1[2], s1[3], al[3]);
#pragma unroll
                for (int ndp = 0; ndp < 4; ndp++) {
                    uint32_t vb = (uint32_t)((ks2 * 16 + arow) * (ASTR * 2) + ndp * 32 + acolb);
                    uint32_t vh[4];
                    LDM_X4T(vh, vB + vb);
                    mma_f16(oa[2 * ndp], ah, &vh[0]);
                    mma_f16(oa[2 * ndp], al, &vh[0]);
                    mma_f16(oa[2 * ndp + 1], ah, &vh[2]);
                    mma_f16(oa[2 * ndp + 1], al, &vh[2]);
                }
            }
        } else {
            // ---- far tile (|dd| == 3): decay <= gamma^129 -> 1-term ----
#pragma unroll
            for (int ks = 0; ks < 4; ks++) {
#pragma unroll
                for (int np = 0; np < 4; np++) {
                    uint32_t bb = (uint32_t)((np * 16 + krow) * (ASTR * 2) + ks * 32 + kcolb);
                    uint32_t kh[4];
                    LDM_X4(kh, kB + bb);
                    mma_f16(sreg[2 * np], qh[ks], &kh[0]);
                    mma_f16(sreg[2 * np + 1], qh[ks], &kh[2]);
                }
            }
#pragma unroll
            for (int nt = 0; nt < 8; nt++) {
                int base = i0 - (kt * 64 + nt * 8 + 2 * tc) + 255;
                sreg[nt][0] *= sDec[base];
                sreg[nt][1] *= sDec[base - 1];
                sreg[nt][2] *= sDec[base + 8];
                sreg[nt][3] *= sDec[base + 7];
            }
#pragma unroll
            for (int ks2 = 0; ks2 < 4; ks2++) {
                float* s0 = sreg[2 * ks2];
                float* s1 = sreg[2 * ks2 + 1];
                uint32_t ah[4];
                ah[0] = packf16(s0[0], s0[1]);
                ah[1] = packf16(s0[2], s0[3]);
                ah[2] = packf16(s1[0], s1[1]);
                ah[3] = packf16(s1[2], s1[3]);
#pragma unroll
                for (int ndp = 0; ndp < 4; ndp++) {
                    uint32_t vb = (uint32_t)((ks2 * 16 + arow) * (ASTR * 2) + ndp * 32 + acolb);
                    uint32_t vh[4];
                    LDM_X4T(vh, vB + vb);
                    mma_f16(oa[2 * ndp], ah, &vh[0]);
                    mma_f16(oa[2 * ndp + 1], ah, &vh[2]);
                }
            }
        }
        __syncthreads();
    }

    // store O
#pragma unroll
    for (int nd = 0; nd < 8; nd++) {
        int c = nd * 8 + 2 * tc;
        int r0 = qsub * 64 + wq * 16 + g;
        *(float2*)&out[(size_t)(gb + r0) * HD + c] = make_float2(oa[nd][0], oa[nd][1]);
        *(float2*)&out[(size_t)(gb + r0 + 8) * HD + c] = make_float2(oa[nd][2], oa[nd][3]);
    }
}

// ---------------- launch ----------------
extern "C" void kernel_launch(void* const* d_in, const int* in_sizes, int n_in,
                              void* d_out, int out_size) {
    const float* X  = (const float*)d_in[0];
    const float* WQ = (const float*)d_in[1];
    const float* WK = (const float*)d_in[2];
    const float* WV = (const float*)d_in[3];
    float* out = (float*)d_out;

    prep_kernel<<<384, 256>>>(WQ, WK, WV);

    cudaFuncSetAttribute(proj_kernel, cudaFuncAttributeMaxDynamicSharedMemorySize, P_TOTAL);
    proj_kernel<<<256, 256, P_TOTAL>>>(X);

    cudaFuncSetAttribute(state_kernel, cudaFuncAttributeMaxDynamicSharedMemorySize, SC_TOTAL);
    state_kernel<<<dim3(7, B), 128, SC_TOTAL>>>();

    cudaFuncSetAttribute(attn_kernel, cudaFuncAttributeMaxDynamicSharedMemorySize, A_TOTAL);
    attn_kernel<<<dim3(16, B), 256, A_TOTAL>>>(out);
}

// round 13
// speedup vs baseline: 1.3025x; 1.0054x over previous
#include <cuda_runtime.h>
#include <cuda_bf16.h>
#include <cuda_fp16.h>
#include <math.h>
#include <stdint.h>

#define B 8
#define SEQ 2048
#define HID 512
#define HD 64
#define LGAM -0.04580369f   // log2(0.96875)

// ---------------- scratch (device globals; no allocation allowed) ----------------
__device__ __align__(256) uint16_t gQh[B * SEQ * HD], gQl[B * SEQ * HD];  // fp16 hi/lo
__device__ __align__(256) uint16_t gKf[B * SEQ * HD];                     // fp16 single
__device__ __align__(256) uint16_t gVf[B * SEQ * HD];                     // fp16 single
__device__ __align__(256) uint16_t gWf[192 * HID];     // fp16 W, [region*64+d][k]
__device__ __align__(256) float gC[B * 8 * HD * HD];   // chunk KV states, fp32
__device__ float tQc[SEQ * 32], tQs[SEQ * 32], tKc[SEQ * 32], tKs[SEQ * 32];

// ---------------- helpers ----------------
__device__ __forceinline__ void mma_f16(float* d, const uint32_t* a, const uint32_t* b) {
    asm volatile(
        "mma.sync.aligned.m16n8k16.row.col.f32.f16.f16.f32 "
        "{%0,%1,%2,%3}, {%4,%5,%6,%7}, {%8,%9}, {%0,%1,%2,%3};"
        : "+f"(d[0]), "+f"(d[1]), "+f"(d[2]), "+f"(d[3])
        : "r"(a[0]), "r"(a[1]), "r"(a[2]), "r"(a[3]), "r"(b[0]), "r"(b[1]));
}
#define LDM_X4(R, a) \
    asm volatile("ldmatrix.sync.aligned.m8n8.x4.shared.b16 {%0,%1,%2,%3}, [%4];" \
                 : "=r"((R)[0]), "=r"((R)[1]), "=r"((R)[2]), "=r"((R)[3]) : "r"(a))
#define LDM_X4T(R, a) \
    asm volatile("ldmatrix.sync.aligned.m8n8.x4.trans.shared.b16 {%0,%1,%2,%3}, [%4];" \
                 : "=r"((R)[0]), "=r"((R)[1]), "=r"((R)[2]), "=r"((R)[3]) : "r"(a))
#define CPA16(dst, src) \
    asm volatile("cp.async.ca.shared.global [%0], [%1], 16;" \
                 :: "r"(dst), "l"(__cvta_generic_to_global(src)))
#define CPA_COMMIT() asm volatile("cp.async.commit_group;")
#define CPA_WAIT1() asm volatile("cp.async.wait_group 1;")
#define CPA_WAIT0() asm volatile("cp.async.wait_group 0;")
__device__ __forceinline__ uint32_t smem_u32(const void* p) {
    uint32_t a;
    asm("{ .reg .u64 t; cvta.to.shared.u64 t, %1; cvt.u32.u64 %0, t; }" : "=r"(a) : "l"(p));
    return a;
}
__device__ __forceinline__ uint32_t packf16(float x0, float x1) {
    __half2 h = __floats2half2_rn(x0, x1);
    return *reinterpret_cast<uint32_t*>(&h);
}
__device__ __forceinline__ uint32_t splitf16(float x0, float x1, uint32_t& lo) {
    __half2 h = __floats2half2_rn(x0, x1);
    float2 hf = __half22float2(h);
    __half2 l = __floats2half2_rn(x0 - hf.x, x1 - hf.y);
    lo = *reinterpret_cast<uint32_t*>(&l);
    return *reinterpret_cast<uint32_t*>(&h);
}

// ---------------- kernel 0: xPos tables (fast-math) + W fp16 ----------------
__global__ void prep_kernel(const float* __restrict__ WQ,
                            const float* __restrict__ WK,
                            const float* __restrict__ WV) {
    int idx = blockIdx.x * blockDim.x + threadIdx.x;
    if (idx < SEQ * 32) {
        int t = idx >> 5;
        int m = idx & 31;
        float sv = (2.0f * (float)m + 0.4f * (float)HD) / (1.4f * (float)HD);
        float p = ((float)t * (1.0f / 512.0f)) * log2f(sv);
        float s = exp2f(p);
        float rs = exp2f(-p);
        // invf = 10000^(-m/32) = 2^(-m * log2(1e4)/32); phase-error diluted over dims
        float invf = exp2f(-(float)m * 0.41524101f);
        float sn, cs;
        __sincosf((float)t * invf, &sn, &cs);
        tQc[idx] = cs * s;
        tQs[idx] = sn * s;
        tKc[idx] = cs * rs;
        tKs[idx] = sn * rs;
    }
    if (idx < 3 * HID * HD) {
        int region = idx >> 15;
        int k = (idx & 32767) >> 6;
        int d = idx & 63;
        const float* W = (region == 0) ? WQ : ((region == 1) ? WK : WV);
        __half hw = __float2half_rn(W[k * HD + d]);
        gWf[(region * 64 + d) * HID + k] = *reinterpret_cast<uint16_t*>(&hw);
    }
}

// ---------------- kernel 1: QKV projection, fp16 1-term HMMA + xPos ----------------
// 256 CTAs x 256 thr (8 warps 2x4). CTA tile 64x192, warp tile 32x48.
#define PSTR 72
#define P_WB(s) ((s) * 27648)
#define P_A 55296
#define P_TOTAL 64512

__global__ __launch_bounds__(256, 2) void proj_kernel(const float* __restrict__ X) {
    extern __shared__ char sm[];
    uint16_t* Ah = (uint16_t*)(sm + P_A);
    uint32_t smb = smem_u32(sm);

    int tid = threadIdx.x;
    int wid = tid >> 5, lane = tid & 31;
    int wm = wid >> 2, wn = wid & 3;
    int g = lane >> 2, tc = lane & 3;

    int arow = lane & 15;
    int acolb = (lane >> 4) * 16;
    int krow = (lane & 7) + ((lane >> 4) << 3);
    int kcolb = ((lane >> 3) & 1) * 16;

    const float* Xb = X + (size_t)blockIdx.x * 64 * HID;

    float acc[2][6][4];
#pragma unroll
    for (int mt = 0; mt < 2; mt++)
#pragma unroll
        for (int nt = 0; nt < 6; nt++)
#pragma unroll
            for (int i = 0; i < 4; i++) acc[mt][nt][i] = 0.0f;

    float4 xr[4];
#pragma unroll
    for (int it = 0; it < 4; it++) {
        int e = tid + it * 256;
        int r = e >> 4, c = e & 15;
        xr[it] = *(const float4*)&Xb[r * HID + c * 4];
    }
#pragma unroll
    for (int it = 0; it < 6; it++) {
        int e = tid + it * 256;
        int r = e >> 3, c = e & 7;
        CPA16(smb + P_WB(0) + r * 144 + c * 16, &gWf[r * HID + c * 8]);
    }
    CPA_COMMIT();

    for (int chunk = 0; chunk < 8; chunk++) {
        int s = chunk & 1;
        int k0n = (chunk + 1) * 64;
        if (chunk < 7) {
#pragma unroll
            for (int it = 0; it < 6; it++) {
                int e = tid + it * 256;
                int r = e >> 3, c = e & 7;
                CPA16(smb + P_WB(s ^ 1) + r * 144 + c * 16, &gWf[r * HID + k0n + c * 8]);
            }
            CPA_COMMIT();
        }
#pragma unroll
        for (int it = 0; it < 4; it++) {
            int e = tid + it * 256;
            int r = e >> 4, c = e & 15;
            float4 v = xr[it];
            *(uint2*)&Ah[r * PSTR + 4 * c] =
                make_uint2(packf16(v.x, v.y), packf16(v.z, v.w));
        }
        if (chunk < 7) {
#pragma unroll
            for (int it = 0; it < 4; it++) {
                int e = tid + it * 256;
                int r = e >> 4, c = e & 15;
                xr[it] = *(const float4*)&Xb[r * HID + k0n + c * 4];
            }
        }
        if (chunk < 7) { CPA_WAIT1(); } else { CPA_WAIT0(); }
        __syncthreads();

        uint32_t wbase = smb + P_WB(s);
#pragma unroll
        for (int ks = 0; ks < 4; ks++) {
            uint32_t ah[2][4];
#pragma unroll
            for (int mt = 0; mt < 2; mt++) {
                uint32_t rb = (uint32_t)((wm * 32 + mt * 16 + arow) * (PSTR * 2) + ks * 32 + acolb);
                LDM_X4(ah[mt], smb + P_A + rb);
            }
#pragma unroll
            for (int np = 0; np < 3; np++) {
                int n = wn * 48 + np * 16;
                uint32_t bb = (uint32_t)((n + krow) * (PSTR * 2) + ks * 32 + kcolb);
                uint32_t bf[4];
                LDM_X4(bf, wbase + bb);
#pragma unroll
                for (int mt = 0; mt < 2; mt++) {
                    mma_f16(acc[mt][2 * np], ah[mt], &bf[0]);
                    mma_f16(acc[mt][2 * np + 1], ah[mt], &bf[2]);
                }
            }
        }
        __syncthreads();
    }

    // epilogue: rotary, then Q -> fp16 hi/lo, K/V -> fp16 single
#pragma unroll
    for (int mt = 0; mt < 2; mt++) {
#pragma unroll
        for (int half = 0; half < 2; half++) {
            int lrow = wm * 32 + mt * 16 + g + half * 8;
            int grow = blockIdx.x * 64 + lrow;
            int tpos = grow & (SEQ - 1);
#pragma unroll
            for (int nt = 0; nt < 6; nt++) {
                int c = wn * 48 + nt * 8 + 2 * tc;
                float v0 = acc[mt][nt][half * 2];
                float v1 = acc[mt][nt][half * 2 + 1];
                if (c < 64) {
                    int m = c >> 1;
                    float cs = tQc[tpos * 32 + m], sn = tQs[tpos * 32 + m];
                    float o0 = v0 * cs - v1 * sn;
                    float o1 = v1 * cs + v0 * sn;
                    uint32_t lo;
                    uint32_t hi = splitf16(o0, o1, lo);
                    ((uint32_t*)gQh)[grow * 32 + m] = hi;
                    ((uint32_t*)gQl)[grow * 32 + m] = lo;
                } else if (c < 128) {
                    int m = (c - 64) >> 1;
                    float cs = tKc[tpos * 32 + m], sn = tKs[tpos * 32 + m];
                    float o0 = v0 * cs - v1 * sn;
                    float o1 = v1 * cs + v0 * sn;
                    ((uint32_t*)gKf)[grow * 32 + m] = packf16(o0, o1);
                } else {
                    int m = (c - 128) >> 1;
                    ((uint32_t*)gVf)[grow * 32 + m] = packf16(v0, v1);
                }
            }
        }
    }
}

// ---------------- kernel 1.5: chunk KV state C_c (fp16 1-term) ----------------
#define SC_K 0
#define SC_V 9216
#define SC_TOTAL 18432

__global__ __launch_bounds__(128) void state_kernel() {
    extern __shared__ char sm[];
    uint32_t smb = smem_u32(sm);
    int c = blockIdx.x, b = blockIdx.y;
    int tid = threadIdx.x;
    int wid = tid >> 5, lane = tid & 31;
    int g = lane >> 2, tc = lane & 3;

    int arow = lane & 15;
    int acolb = (lane >> 4) * 16;
    int krow = (lane & 7) + ((lane >> 4) << 3);
    int kcolb = ((lane >> 3) & 1) * 16;

    float acc[8][4];
#pragma unroll
    for (int nd = 0; nd < 8; nd++)
#pragma unroll
        for (int i = 0; i < 4; i++) acc[nd][i] = 0.0f;

    for (int jt = 0; jt < 4; jt++) {
        __syncthreads();
        int jb = b * SEQ + c * 256 + jt * 64;
#pragma unroll
        for (int it = 0; it < 4; it++) {
            int e = tid + it * 128;
            int r = e >> 3, cc = e & 7;
            *(float4*)(sm + SC_K + r * 144 + cc * 16) = *(const float4*)&gKf[(size_t)(jb + r) * HD + cc * 8];
        }
#pragma unroll
        for (int it = 0; it < 16; it++) {
            int p = tid + it * 128;
            int r = p >> 5, vp = p & 31;
            uint32_t u = ((const uint32_t*)gVf)[(size_t)(jb + r) * 32 + vp];
            __half2 hv = *reinterpret_cast<__half2*>(&u);
            float2 f = __half22float2(hv);
            float w = exp2f(LGAM * (float)(256 - (jt * 64 + r)));
            *(uint32_t*)(sm + SC_V + r * 144 + vp * 4) = packf16(w * f.x, w * f.y);
        }
        __syncthreads();

#pragma unroll
        for (int ks = 0; ks < 4; ks++) {
            uint32_t ab = (uint32_t)((ks * 16 + krow) * 144 + wid * 32 + kcolb);
            uint32_t ah[4];
            LDM_X4T(ah, smb + SC_K + ab);
#pragma unroll
            for (int ndp = 0; ndp < 4; ndp++) {
                uint32_t vb = (uint32_t)((ks * 16 + arow) * 144 + ndp * 32 + acolb);
                uint32_t vh[4];
                LDM_X4T(vh, smb + SC_V + vb);
                mma_f16(acc[2 * ndp], ah, &vh[0]);
                mma_f16(acc[2 * ndp + 1], ah, &vh[2]);
            }
        }
    }

    float* Cb = gC + ((size_t)(b * 8 + c)) * 4096;
#pragma unroll
    for (int nd = 0; nd < 8; nd++) {
        int v = nd * 8 + 2 * tc;
        int d0 = wid * 16 + g;
        *(float2*)&Cb[d0 * 64 + v] = make_float2(acc[nd][0], acc[nd][1]);
        *(float2*)&Cb[(d0 + 8) * 64 + v] = make_float2(acc[nd][2], acc[nd][3]);
    }
}

// ---------------- kernel 2: retention attention (16 warps, k-split pairs) ----------------
// grid (16, 8) x 512 thr. Row-group rg = wid>>1 (16 q-rows), half = wid&1.
// half0: state apply + tiles {0,1}; half1: tiles {2,3}; O partials summed via smem.
#define A_QH 0            // 128 x 144B
#define A_QL 18432
#define A_MH 36864        // 64 x 144B
#define A_ML 46080
#define A_K 55296         // 256 x 144B
#define A_V 92160
#define A_DEC 129024      // 511 floats
#define A_TOTAL 131072
#define REDSTR 1088       // reduction block stride (floats), padded

__global__ __launch_bounds__(512, 1) void attn_kernel(float* __restrict__ out) {
    extern __shared__ char sm[];
    uint16_t* Qh = (uint16_t*)(sm + A_QH);
    uint16_t* Ql = (uint16_t*)(sm + A_QL);
    float* sDec = (float*)(sm + A_DEC);
    uint32_t smb = smem_u32(sm);

    int qtp = blockIdx.x, b = blockIdx.y;
    int tid = threadIdx.x;
    int wid = tid >> 5, lane = tid & 31;
    int rg = wid >> 1, half = wid & 1;
    int qsub = rg >> 2, wq = rg & 3;
    int g = lane >> 2, tc = lane & 3;
    int q0 = qtp * 128;
    int gb = b * SEQ + q0;
    int chunk = qtp >> 1;
    int qt_w = qtp * 2 + qsub;

    int arow = lane & 15;
    int acolb = (lane >> 4) * 16;
    int krow = (lane & 7) + ((lane >> 4) << 3);
    int kcolb = ((lane >> 3) & 1) * 16;

    // ---- stage ALL 4 K/V tiles (whole chunk, 256 rows) ----
    {
        int kb0 = b * SEQ + chunk * 256;
#pragma unroll
        for (int it = 0; it < 4; it++) {
            int e = tid + it * 512;
            int r = e >> 3, c = e & 7;
            uint32_t off = (uint32_t)(r * 144 + c * 16);
            CPA16(smb + A_K + off, &gKf[(size_t)(kb0 + r) * HD + c * 8]);
            CPA16(smb + A_V + off, &gVf[(size_t)(kb0 + r) * HD + c * 8]);
        }
        CPA_COMMIT();
    }

    // Q (128 rows fp16 hi/lo), decay window, state M
#pragma unroll
    for (int it = 0; it < 2; it++) {
        int e = tid + it * 512;
        int r = e >> 3, c = e & 7;
        *(float4*)&Qh[r * 72 + c * 8] = *(const float4*)&gQh[(size_t)(gb + r) * HD + c * 8];
        *(float4*)&Ql[r * 72 + c * 8] = *(const float4*)&gQl[(size_t)(gb + r) * HD + c * 8];
    }
    if (tid < 511) sDec[tid] = exp2f(LGAM * fabsf((float)(tid - 255)));
    if (chunk >= 1) {
        const float2* C1 = (const float2*)(gC + ((size_t)(b * 8 + chunk - 1)) * 4096);
        const float2* C2 = (chunk >= 2) ? (const float2*)(gC + ((size_t)(b * 8 + chunk - 2)) * 4096) : (const float2*)0;
        const float G256 = 2.952517e-4f;   // gamma^256
#pragma unroll
        for (int it = 0; it < 4; it++) {
            int p = tid + it * 512;
            int d = p >> 5, vp = p & 31;
            float2 v = C1[p];
            if (C2) {
                float2 w = C2[p];
                v.x += G256 * w.x;
                v.y += G256 * w.y;
            }
            uint32_t lo;
            uint32_t hi = splitf16(v.x, v.y, lo);
            *(uint32_t*)(sm + A_MH + d * 144 + vp * 4) = hi;
            *(uint32_t*)(sm + A_ML + d * 144 + vp * 4) = lo;
        }
    }
    __syncthreads();

    // Q fragments (both halves load the same rows)
    uint32_t qh[4][4], ql[4][4];
#pragma unroll
    for (int ks = 0; ks < 4; ks++) {
        uint32_t rb = (uint32_t)((qsub * 64 + wq * 16 + arow) * 144 + ks * 32 + acolb);
        LDM_X4(qh[ks], smb + A_QH + rb);
        LDM_X4(ql[ks], smb + A_QL + rb);
    }

    float oa[8][4];
#pragma unroll
    for (int nd = 0; nd < 8; nd++)
#pragma unroll
        for (int i = 0; i < 4; i++) oa[nd][i] = 0.0f;

    int i0 = q0 + qsub * 64 + wq * 16 + g;

    // ---- state apply (half0 only): O += gamma^(i-c0) * Q @ M ----
    if (chunk >= 1 && half == 0) {
        float T[8][4];
#pragma unroll
        for (int nd = 0; nd < 8; nd++)
#pragma unroll
            for (int i = 0; i < 4; i++) T[nd][i] = 0.0f;
#pragma unroll
        for (int ks = 0; ks < 4; ks++) {
#pragma unroll
            for (int ndp = 0; ndp < 4; ndp++) {
                uint32_t vb = (uint32_t)((ks * 16 + arow) * 144 + ndp * 32 + acolb);
                uint32_t mh[4], ml[4];
                LDM_X4T(mh, smb + A_MH + vb);
                LDM_X4T(ml, smb + A_ML + vb);
                mma_f16(T[2 * ndp], qh[ks], &mh[0]);
                mma_f16(T[2 * ndp], qh[ks], &ml[0]);
                mma_f16(T[2 * ndp], ql[ks], &mh[0]);
                mma_f16(T[2 * ndp + 1], qh[ks], &mh[2]);
                mma_f16(T[2 * ndp + 1], qh[ks], &ml[2]);
                mma_f16(T[2 * ndp + 1], ql[ks], &mh[2]);
            }
        }
        int c0 = chunk * 256;
        float sc0 = sDec[i0 - c0 + 255];
        float sc1 = sDec[i0 + 8 - c0 + 255];
#pragma unroll
        for (int nd = 0; nd < 8; nd++) {
            oa[nd][0] += sc0 * T[nd][0];
            oa[nd][1] += sc0 * T[nd][1];
            oa[nd][2] += sc1 * T[nd][2];
            oa[nd][3] += sc1 * T[nd][3];
        }
    }

    CPA_WAIT0();
    __syncthreads();

    // ---- 2 intra-chunk tiles per half warp ----
#pragma unroll
    for (int ii = 0; ii < 2; ii++) {
        int i = half * 2 + ii;
        int kt = chunk * 4 + i;
        int dd = qt_w - kt;
        bool nr = (dd <= 2) && (dd >= -2);
        uint32_t kB = smb + A_K + (uint32_t)(i * 64 * 144);
        uint32_t vB = smb + A_V + (uint32_t)(i * 64 * 144);

        float sreg[8][4];
#pragma unroll
        for (int nt = 0; nt < 8; nt++)
#pragma unroll
            for (int jj = 0; jj < 4; jj++) sreg[nt][jj] = 0.0f;

        if (nr) {
#pragma unroll
            for (int ks = 0; ks < 4; ks++) {
#pragma unroll
                for (int np = 0; np < 4; np++) {
                    uint32_t bb = (uint32_t)((np * 16 + krow) * 144 + ks * 32 + kcolb);
                    uint32_t kh[4];
                    LDM_X4(kh, kB + bb);
                    mma_f16(sreg[2 * np], qh[ks], &kh[0]);
                    mma_f16(sreg[2 * np], ql[ks], &kh[0]);
                    mma_f16(sreg[2 * np + 1], qh[ks], &kh[2]);
                    mma_f16(sreg[2 * np + 1], ql[ks], &kh[2]);
                }
            }
#pragma unroll
            for (int nt = 0; nt < 8; nt++) {
                int base = i0 - (kt * 64 + nt * 8 + 2 * tc) + 255;
                sreg[nt][0] *= sDec[base];
                sreg[nt][1] *= sDec[base - 1];
                sreg[nt][2] *= sDec[base + 8];
                sreg[nt][3] *= sDec[base + 7];
            }
#pragma unroll
            for (int ks2 = 0; ks2 < 4; ks2++) {
                float* s0 = sreg[2 * ks2];
                float* s1 = sreg[2 * ks2 + 1];
                uint32_t ah[4], al[4];
                ah[0] = splitf16(s0[0], s0[1], al[0]);
                ah[1] = splitf16(s0[2], s0[3], al[1]);
                ah[2] = splitf16(s1[0], s1[1], al[2]);
                ah[3] = splitf16(s1[2], s1[3], al[3]);
#pragma unroll
                for (int ndp = 0; ndp < 4; ndp++) {
                    uint32_t vb = (uint32_t)((ks2 * 16 + arow) * 144 + ndp * 32 + acolb);
                    uint32_t vh[4];
                    LDM_X4T(vh, vB + vb);
                    mma_f16(oa[2 * ndp], ah, &vh[0]);
                    mma_f16(oa[2 * ndp], al, &vh[0]);
                    mma_f16(oa[2 * ndp + 1], ah, &vh[2]);
                    mma_f16(oa[2 * ndp + 1], al, &vh[2]);
                }
            }
        } else {
            // far tile (|dd| == 3): decay <= gamma^129 -> 1-term
#pragma unroll
            for (int ks = 0; ks < 4; ks++) {
#pragma unroll
                for (int np = 0; np < 4; np++) {
                    uint32_t bb = (uint32_t)((np * 16 + krow) * 144 + ks * 32 + kcolb);
                    uint32_t kh[4];
                    LDM_X4(kh, kB + bb);
                    mma_f16(sreg[2 * np], qh[ks], &kh[0]);
                    mma_f16(sreg[2 * np + 1], qh[ks], &kh[2]);
                }
            }
#pragma unroll
            for (int nt = 0; nt < 8; nt++) {
                int base = i0 - (kt * 64 + nt * 8 + 2 * tc) + 255;
                sreg[nt][0] *= sDec[base];
                sreg[nt][1] *= sDec[base - 1];
                sreg[nt][2] *= sDec[base + 8];
                sreg[nt][3] *= sDec[base + 7];
            }
#pragma unroll
            for (int ks2 = 0; ks2 < 4; ks2++) {
                float* s0 = sreg[2 * ks2];
                float* s1 = sreg[2 * ks2 + 1];
                uint32_t ah[4];
                ah[0] = packf16(s0[0], s0[1]);
                ah[1] = packf16(s0[2], s0[3]);
                ah[2] = packf16(s1[0], s1[1]);
                ah[3] = packf16(s1[2], s1[3]);
#pragma unroll
                for (int ndp = 0; ndp < 4; ndp++) {
                    uint32_t vb = (uint32_t)((ks2 * 16 + arow) * 144 + ndp * 32 + acolb);
                    uint32_t vh[4];
                    LDM_X4T(vh, vB + vb);
                    mma_f16(oa[2 * ndp], ah, &vh[0]);
                    mma_f16(oa[2 * ndp + 1], ah, &vh[2]);
                }
            }
        }
    }

    // ---- combine half0 + half1 partials via smem (reuse K region) ----
    __syncthreads();   // all tile reads of K/V done
    float* red = (float*)(sm + A_K) + rg * REDSTR;
    if (half == 1) {
#pragma unroll
        for (int nd = 0; nd < 8; nd++) {
            int c = nd * 8 + 2 * tc;
            red[g * 68 + c] = oa[nd][0];
            red[g * 68 + c + 1] = oa[nd][1];
            red[(g + 8) * 68 + c] = oa[nd][2];
            red[(g + 8) * 68 + c + 1] = oa[nd][3];
        }
    }
    __syncthreads();
    if (half == 0) {
#pragma unroll
        for (int nd = 0; nd < 8; nd++) {
            int c = nd * 8 + 2 * tc;
            oa[nd][0] += red[g * 68 + c];
            oa[nd][1] += red[g * 68 + c + 1];
            oa[nd][2] += red[(g + 8) * 68 + c];
            oa[nd][3] += red[(g + 8) * 68 + c + 1];
        }
        int r0 = qsub * 64 + wq * 16 + g;
#pragma unroll
        for (int nd = 0; nd < 8; nd++) {
            int c = nd * 8 + 2 * tc;
            *(float2*)&out[(size_t)(gb + r0) * HD + c] = make_float2(oa[nd][0], oa[nd][1]);
            *(float2*)&out[(size_t)(gb + r0 + 8) * HD + c] = make_float2(oa[nd][2], oa[nd][3]);
        }
    }
}

// ---------------- launch ----------------
extern "C" void kernel_launch(void* const* d_in, const int* in_sizes, int n_in,
                              void* d_out, int out_size) {
    const float* X  = (const float*)d_in[0];
    const float* WQ = (const float*)d_in[1];
    const float* WK = (const float*)d_in[2];
    const float* WV = (const float*)d_in[3];
    float* out = (float*)d_out;

    prep_kernel<<<384, 256>>>(WQ, WK, WV);

    cudaFuncSetAttribute(proj_kernel, cudaFuncAttributeMaxDynamicSharedMemorySize, P_TOTAL);
    proj_kernel<<<256, 256, P_TOTAL>>>(X);

    cudaFuncSetAttribute(state_kernel, cudaFuncAttributeMaxDynamicSharedMemorySize, SC_TOTAL);
    state_kernel<<<dim3(7, B), 128, SC_TOTAL>>>();

    cudaFuncSetAttribute(attn_kernel, cudaFuncAttributeMaxDynamicSharedMemorySize, A_TOTAL);
    attn_kernel<<<dim3(16, B), 512, A_TOTAL>>>(out);
}

// round 14
// speedup vs baseline: 1.3624x; 1.0460x over previous
#include <cuda_runtime.h>
#include <cuda_bf16.h>
#include <cuda_fp16.h>
#include <math.h>
#include <stdint.h>

#define B 8
#define SEQ 2048
#define HID 512
#define HD 64
#define LGAM -0.04580369f   // log2(0.96875)

// ---------------- scratch (device globals; no allocation allowed) ----------------
__device__ __align__(256) uint16_t gQf[B * SEQ * HD];   // fp16 single
__device__ __align__(256) uint16_t gKf[B * SEQ * HD];   // fp16 single
__device__ __align__(256) uint16_t gVf[B * SEQ * HD];   // fp16 single
__device__ __align__(256) uint16_t gWf[192 * HID];      // fp16 W, [region*64+d][k]
__device__ __align__(256) float gC[B * 8 * HD * HD];    // chunk KV states, fp32
__device__ float tQc[SEQ * 32], tQs[SEQ * 32], tKc[SEQ * 32], tKs[SEQ * 32];

// ---------------- helpers ----------------
__device__ __forceinline__ void mma_f16(float* d, const uint32_t* a, const uint32_t* b) {
    asm volatile(
        "mma.sync.aligned.m16n8k16.row.col.f32.f16.f16.f32 "
        "{%0,%1,%2,%3}, {%4,%5,%6,%7}, {%8,%9}, {%0,%1,%2,%3};"
        : "+f"(d[0]), "+f"(d[1]), "+f"(d[2]), "+f"(d[3])
        : "r"(a[0]), "r"(a[1]), "r"(a[2]), "r"(a[3]), "r"(b[0]), "r"(b[1]));
}
#define LDM_X4(R, a) \
    asm volatile("ldmatrix.sync.aligned.m8n8.x4.shared.b16 {%0,%1,%2,%3}, [%4];" \
                 : "=r"((R)[0]), "=r"((R)[1]), "=r"((R)[2]), "=r"((R)[3]) : "r"(a))
#define LDM_X4T(R, a) \
    asm volatile("ldmatrix.sync.aligned.m8n8.x4.trans.shared.b16 {%0,%1,%2,%3}, [%4];" \
                 : "=r"((R)[0]), "=r"((R)[1]), "=r"((R)[2]), "=r"((R)[3]) : "r"(a))
#define CPA16(dst, src) \
    asm volatile("cp.async.ca.shared.global [%0], [%1], 16;" \
                 :: "r"(dst), "l"(__cvta_generic_to_global(src)))
#define CPA_COMMIT() asm volatile("cp.async.commit_group;")
#define CPA_WAIT1() asm volatile("cp.async.wait_group 1;")
#define CPA_WAIT0() asm volatile("cp.async.wait_group 0;")
__device__ __forceinline__ uint32_t smem_u32(const void* p) {
    uint32_t a;
    asm("{ .reg .u64 t; cvta.to.shared.u64 t, %1; cvt.u32.u64 %0, t; }" : "=r"(a) : "l"(p));
    return a;
}
__device__ __forceinline__ uint32_t packf16(float x0, float x1) {
    __half2 h = __floats2half2_rn(x0, x1);
    return *reinterpret_cast<uint32_t*>(&h);
}
__device__ __forceinline__ uint32_t splitf16(float x0, float x1, uint32_t& lo) {
    __half2 h = __floats2half2_rn(x0, x1);
    float2 hf = __half22float2(h);
    __half2 l = __floats2half2_rn(x0 - hf.x, x1 - hf.y);
    lo = *reinterpret_cast<uint32_t*>(&l);
    return *reinterpret_cast<uint32_t*>(&h);
}

// ---------------- kernel 0: xPos tables (fast-math) + W fp16 (coalesced) ----------------
__global__ void prep_kernel(const float* __restrict__ WQ,
                            const float* __restrict__ WK,
                            const float* __restrict__ WV) {
    int idx = blockIdx.x * blockDim.x + threadIdx.x;
    if (idx < SEQ * 32) {
        int t = idx >> 5;
        int m = idx & 31;
        float sv = (2.0f * (float)m + 0.4f * (float)HD) / (1.4f * (float)HD);
        float p = ((float)t * (1.0f / 512.0f)) * log2f(sv);
        float s = exp2f(p);
        float rs = exp2f(-p);
        float invf = exp2f(-(float)m * 0.41524101f);
        float sn, cs;
        __sincosf((float)t * invf, &sn, &cs);
        tQc[idx] = cs * s;
        tQs[idx] = sn * s;
        tKc[idx] = cs * rs;
        tKs[idx] = sn * rs;
    }
    // W split: k innermost -> coalesced gWf writes (d-innermost was 32x sector waste)
    if (idx < 3 * HID * HD) {
        int region = idx >> 15;
        int d = (idx >> 9) & 63;
        int k = idx & 511;
        const float* W = (region == 0) ? WQ : ((region == 1) ? WK : WV);
        __half hw = __float2half_rn(W[k * HD + d]);
        gWf[(region * 64 + d) * HID + k] = *reinterpret_cast<uint16_t*>(&hw);
    }
}

// ---------------- kernel 1: QKV projection, fp16 1-term HMMA + xPos ----------------
// 256 CTAs x 256 thr (8 warps 2x4). CTA tile 64x192, warp tile 32x48.
#define PSTR 72
#define P_WB(s) ((s) * 27648)
#define P_A 55296
#define P_TOTAL 64512

__global__ __launch_bounds__(256, 2) void proj_kernel(const float* __restrict__ X) {
    extern __shared__ char sm[];
    uint16_t* Ah = (uint16_t*)(sm + P_A);
    uint32_t smb = smem_u32(sm);

    int tid = threadIdx.x;
    int wid = tid >> 5, lane = tid & 31;
    int wm = wid >> 2, wn = wid & 3;
    int g = lane >> 2, tc = lane & 3;

    int arow = lane & 15;
    int acolb = (lane >> 4) * 16;
    int krow = (lane & 7) + ((lane >> 4) << 3);
    int kcolb = ((lane >> 3) & 1) * 16;

    const float* Xb = X + (size_t)blockIdx.x * 64 * HID;

    float acc[2][6][4];
#pragma unroll
    for (int mt = 0; mt < 2; mt++)
#pragma unroll
        for (int nt = 0; nt < 6; nt++)
#pragma unroll
            for (int i = 0; i < 4; i++) acc[mt][nt][i] = 0.0f;

    float4 xr[4];
#pragma unroll
    for (int it = 0; it < 4; it++) {
        int e = tid + it * 256;
        int r = e >> 4, c = e & 15;
        xr[it] = *(const float4*)&Xb[r * HID + c * 4];
    }
#pragma unroll
    for (int it = 0; it < 6; it++) {
        int e = tid + it * 256;
        int r = e >> 3, c = e & 7;
        CPA16(smb + P_WB(0) + r * 144 + c * 16, &gWf[r * HID + c * 8]);
    }
    CPA_COMMIT();

    for (int chunk = 0; chunk < 8; chunk++) {
        int s = chunk & 1;
        int k0n = (chunk + 1) * 64;
        if (chunk < 7) {
#pragma unroll
            for (int it = 0; it < 6; it++) {
                int e = tid + it * 256;
                int r = e >> 3, c = e & 7;
                CPA16(smb + P_WB(s ^ 1) + r * 144 + c * 16, &gWf[r * HID + k0n + c * 8]);
            }
            CPA_COMMIT();
        }
#pragma unroll
        for (int it = 0; it < 4; it++) {
            int e = tid + it * 256;
            int r = e >> 4, c = e & 15;
            float4 v = xr[it];
            *(uint2*)&Ah[r * PSTR + 4 * c] =
                make_uint2(packf16(v.x, v.y), packf16(v.z, v.w));
        }
        if (chunk < 7) {
#pragma unroll
            for (int it = 0; it < 4; it++) {
                int e = tid + it * 256;
                int r = e >> 4, c = e & 15;
                xr[it] = *(const float4*)&Xb[r * HID + k0n + c * 4];
            }
        }
        if (chunk < 7) { CPA_WAIT1(); } else { CPA_WAIT0(); }
        __syncthreads();

        uint32_t wbase = smb + P_WB(s);
#pragma unroll
        for (int ks = 0; ks < 4; ks++) {
            uint32_t ah[2][4];
#pragma unroll
            for (int mt = 0; mt < 2; mt++) {
                uint32_t rb = (uint32_t)((wm * 32 + mt * 16 + arow) * (PSTR * 2) + ks * 32 + acolb);
                LDM_X4(ah[mt], smb + P_A + rb);
            }
#pragma unroll
            for (int np = 0; np < 3; np++) {
                int n = wn * 48 + np * 16;
                uint32_t bb = (uint32_t)((n + krow) * (PSTR * 2) + ks * 32 + kcolb);
                uint32_t bf[4];
                LDM_X4(bf, wbase + bb);
#pragma unroll
                for (int mt = 0; mt < 2; mt++) {
                    mma_f16(acc[mt][2 * np], ah[mt], &bf[0]);
                    mma_f16(acc[mt][2 * np + 1], ah[mt], &bf[2]);
                }
            }
        }
        __syncthreads();
    }

    // epilogue: rotary, store Q/K/V fp16 single
#pragma unroll
    for (int mt = 0; mt < 2; mt++) {
#pragma unroll
        for (int half = 0; half < 2; half++) {
            int lrow = wm * 32 + mt * 16 + g + half * 8;
            int grow = blockIdx.x * 64 + lrow;
            int tpos = grow & (SEQ - 1);
#pragma unroll
            for (int nt = 0; nt < 6; nt++) {
                int c = wn * 48 + nt * 8 + 2 * tc;
                float v0 = acc[mt][nt][half * 2];
                float v1 = acc[mt][nt][half * 2 + 1];
                if (c < 64) {
                    int m = c >> 1;
                    float cs = tQc[tpos * 32 + m], sn = tQs[tpos * 32 + m];
                    ((uint32_t*)gQf)[grow * 32 + m] = packf16(v0 * cs - v1 * sn, v1 * cs + v0 * sn);
                } else if (c < 128) {
                    int m = (c - 64) >> 1;
                    float cs = tKc[tpos * 32 + m], sn = tKs[tpos * 32 + m];
                    ((uint32_t*)gKf)[grow * 32 + m] = packf16(v0 * cs - v1 * sn, v1 * cs + v0 * sn);
                } else {
                    int m = (c - 128) >> 1;
                    ((uint32_t*)gVf)[grow * 32 + m] = packf16(v0, v1);
                }
            }
        }
    }
}

// ---------------- kernel 1.5: chunk KV state C_c (fp16 1-term) ----------------
#define SC_K 0
#define SC_V 9216
#define SC_TOTAL 18432

__global__ __launch_bounds__(128) void state_kernel() {
    extern __shared__ char sm[];
    uint32_t smb = smem_u32(sm);
    int c = blockIdx.x, b = blockIdx.y;
    int tid = threadIdx.x;
    int wid = tid >> 5, lane = tid & 31;
    int g = lane >> 2, tc = lane & 3;

    int arow = lane & 15;
    int acolb = (lane >> 4) * 16;
    int krow = (lane & 7) + ((lane >> 4) << 3);
    int kcolb = ((lane >> 3) & 1) * 16;

    float acc[8][4];
#pragma unroll
    for (int nd = 0; nd < 8; nd++)
#pragma unroll
        for (int i = 0; i < 4; i++) acc[nd][i] = 0.0f;

    for (int jt = 0; jt < 4; jt++) {
        __syncthreads();
        int jb = b * SEQ + c * 256 + jt * 64;
#pragma unroll
        for (int it = 0; it < 4; it++) {
            int e = tid + it * 128;
            int r = e >> 3, cc = e & 7;
            *(float4*)(sm + SC_K + r * 144 + cc * 16) = *(const float4*)&gKf[(size_t)(jb + r) * HD + cc * 8];
        }
#pragma unroll
        for (int it = 0; it < 16; it++) {
            int p = tid + it * 128;
            int r = p >> 5, vp = p & 31;
            uint32_t u = ((const uint32_t*)gVf)[(size_t)(jb + r) * 32 + vp];
            __half2 hv = *reinterpret_cast<__half2*>(&u);
            float2 f = __half22float2(hv);
            float w = exp2f(LGAM * (float)(256 - (jt * 64 + r)));
            *(uint32_t*)(sm + SC_V + r * 144 + vp * 4) = packf16(w * f.x, w * f.y);
        }
        __syncthreads();

#pragma unroll
        for (int ks = 0; ks < 4; ks++) {
            uint32_t ab = (uint32_t)((ks * 16 + krow) * 144 + wid * 32 + kcolb);
            uint32_t ah[4];
            LDM_X4T(ah, smb + SC_K + ab);
#pragma unroll
            for (int ndp = 0; ndp < 4; ndp++) {
                uint32_t vb = (uint32_t)((ks * 16 + arow) * 144 + ndp * 32 + acolb);
                uint32_t vh[4];
                LDM_X4T(vh, smb + SC_V + vb);
                mma_f16(acc[2 * ndp], ah, &vh[0]);
                mma_f16(acc[2 * ndp + 1], ah, &vh[2]);
            }
        }
    }

    float* Cb = gC + ((size_t)(b * 8 + c)) * 4096;
#pragma unroll
    for (int nd = 0; nd < 8; nd++) {
        int v = nd * 8 + 2 * tc;
        int d0 = wid * 16 + g;
        *(float2*)&Cb[d0 * 64 + v] = make_float2(acc[nd][0], acc[nd][1]);
        *(float2*)&Cb[(d0 + 8) * 64 + v] = make_float2(acc[nd][2], acc[nd][3]);
    }
}

// ---------------- kernel 2: retention attention (16 warps, k-split pairs, Q fp16) ----------------
// grid (16, 8) x 512 thr. rg = wid>>1 (16 q-rows), half = wid&1.
// half0: state apply + tiles {0,1}; half1: tiles {2,3}; partials summed via smem.
#define A_Q 0             // 128 x 144B
#define A_MH 18432        // 64 x 144B
#define A_ML 27648
#define A_K 36864         // 256 x 144B
#define A_V 73728
#define A_DEC 110592      // 511 floats
#define A_TOTAL 112640
#define REDSTR 1088       // reduction block stride (floats)

__global__ __launch_bounds__(512, 1) void attn_kernel(float* __restrict__ out) {
    extern __shared__ char sm[];
    uint16_t* Qs = (uint16_t*)(sm + A_Q);
    float* sDec = (float*)(sm + A_DEC);
    uint32_t smb = smem_u32(sm);

    int qtp = blockIdx.x, b = blockIdx.y;
    int tid = threadIdx.x;
    int wid = tid >> 5, lane = tid & 31;
    int rg = wid >> 1, half = wid & 1;
    int qsub = rg >> 2, wq = rg & 3;
    int g = lane >> 2, tc = lane & 3;
    int q0 = qtp * 128;
    int gb = b * SEQ + q0;
    int chunk = qtp >> 1;
    int qt_w = qtp * 2 + qsub;

    int arow = lane & 15;
    int acolb = (lane >> 4) * 16;
    int krow = (lane & 7) + ((lane >> 4) << 3);
    int kcolb = ((lane >> 3) & 1) * 16;

    // ---- stage ALL 4 K/V tiles (whole chunk, 256 rows) ----
    {
        int kb0 = b * SEQ + chunk * 256;
#pragma unroll
        for (int it = 0; it < 4; it++) {
            int e = tid + it * 512;
            int r = e >> 3, c = e & 7;
            uint32_t off = (uint32_t)(r * 144 + c * 16);
            CPA16(smb + A_K + off, &gKf[(size_t)(kb0 + r) * HD + c * 8]);
            CPA16(smb + A_V + off, &gVf[(size_t)(kb0 + r) * HD + c * 8]);
        }
        CPA_COMMIT();
    }

    // Q (128 rows fp16), decay window, state M
#pragma unroll
    for (int it = 0; it < 2; it++) {
        int e = tid + it * 512;
        int r = e >> 3, c = e & 7;
        *(float4*)&Qs[r * 72 + c * 8] = *(const float4*)&gQf[(size_t)(gb + r) * HD + c * 8];
    }
    if (tid < 511) sDec[tid] = exp2f(LGAM * fabsf((float)(tid - 255)));
    if (chunk >= 1) {
        const float2* C1 = (const float2*)(gC + ((size_t)(b * 8 + chunk - 1)) * 4096);
        const float2* C2 = (chunk >= 2) ? (const float2*)(gC + ((size_t)(b * 8 + chunk - 2)) * 4096) : (const float2*)0;
        const float G256 = 2.952517e-4f;   // gamma^256
#pragma unroll
        for (int it = 0; it < 4; it++) {
            int p = tid + it * 512;
            int d = p >> 5, vp = p & 31;
            float2 v = C1[p];
            if (C2) {
                float2 w = C2[p];
                v.x += G256 * w.x;
                v.y += G256 * w.y;
            }
            uint32_t lo;
            uint32_t hi = splitf16(v.x, v.y, lo);
            *(uint32_t*)(sm + A_MH + d * 144 + vp * 4) = hi;
            *(uint32_t*)(sm + A_ML + d * 144 + vp * 4) = lo;
        }
    }
    __syncthreads();

    // Q fragments (both halves load the same rows)
    uint32_t qh[4][4];
#pragma unroll
    for (int ks = 0; ks < 4; ks++) {
        uint32_t rb = (uint32_t)((qsub * 64 + wq * 16 + arow) * 144 + ks * 32 + acolb);
        LDM_X4(qh[ks], smb + A_Q + rb);
    }

    float oa[8][4];
#pragma unroll
    for (int nd = 0; nd < 8; nd++)
#pragma unroll
        for (int i = 0; i < 4; i++) oa[nd][i] = 0.0f;

    int i0 = q0 + qsub * 64 + wq * 16 + g;

    // ---- state apply (half0 only): O += gamma^(i-c0) * Q @ (Mh+Ml) ----
    if (chunk >= 1 && half == 0) {
        float T[8][4];
#pragma unroll
        for (int nd = 0; nd < 8; nd++)
#pragma unroll
            for (int i = 0; i < 4; i++) T[nd][i] = 0.0f;
#pragma unroll
        for (int ks = 0; ks < 4; ks++) {
#pragma unroll
            for (int ndp = 0; ndp < 4; ndp++) {
                uint32_t vb = (uint32_t)((ks * 16 + arow) * 144 + ndp * 32 + acolb);
                uint32_t mh[4], ml[4];
                LDM_X4T(mh, smb + A_MH + vb);
                LDM_X4T(ml, smb + A_ML + vb);
                mma_f16(T[2 * ndp], qh[ks], &mh[0]);
                mma_f16(T[2 * ndp], qh[ks], &ml[0]);
                mma_f16(T[2 * ndp + 1], qh[ks], &mh[2]);
                mma_f16(T[2 * ndp + 1], qh[ks], &ml[2]);
            }
        }
        int c0 = chunk * 256;
        float sc0 = sDec[i0 - c0 + 255];
        float sc1 = sDec[i0 + 8 - c0 + 255];
#pragma unroll
        for (int nd = 0; nd < 8; nd++) {
            oa[nd][0] += sc0 * T[nd][0];
            oa[nd][1] += sc0 * T[nd][1];
            oa[nd][2] += sc1 * T[nd][2];
            oa[nd][3] += sc1 * T[nd][3];
        }
    }

    CPA_WAIT0();
    __syncthreads();

    // ---- 2 intra-chunk tiles per half warp ----
#pragma unroll
    for (int ii = 0; ii < 2; ii++) {
        int i = half * 2 + ii;
        int kt = chunk * 4 + i;
        int dd = qt_w - kt;
        bool nr = (dd <= 2) && (dd >= -2);
        uint32_t kB = smb + A_K + (uint32_t)(i * 64 * 144);
        uint32_t vB = smb + A_V + (uint32_t)(i * 64 * 144);

        float sreg[8][4];
#pragma unroll
        for (int nt = 0; nt < 8; nt++)
#pragma unroll
            for (int jj = 0; jj < 4; jj++) sreg[nt][jj] = 0.0f;

        // S = Q K^T (1-term, Q single fp16)
#pragma unroll
        for (int ks = 0; ks < 4; ks++) {
#pragma unroll
            for (int np = 0; np < 4; np++) {
                uint32_t bb = (uint32_t)((np * 16 + krow) * 144 + ks * 32 + kcolb);
                uint32_t kh[4];
                LDM_X4(kh, kB + bb);
                mma_f16(sreg[2 * np], qh[ks], &kh[0]);
                mma_f16(sreg[2 * np + 1], qh[ks], &kh[2]);
            }
        }
        // decay
#pragma unroll
        for (int nt = 0; nt < 8; nt++) {
            int base = i0 - (kt * 64 + nt * 8 + 2 * tc) + 255;
            sreg[nt][0] *= sDec[base];
            sreg[nt][1] *= sDec[base - 1];
            sreg[nt][2] *= sDec[base + 8];
            sreg[nt][3] *= sDec[base + 7];
        }

        if (nr) {
            // O += (Sh+Sl) V (2-term split, in-register)
#pragma unroll
            for (int ks2 = 0; ks2 < 4; ks2++) {
                float* s0 = sreg[2 * ks2];
                float* s1 = sreg[2 * ks2 + 1];
                uint32_t ah[4], al[4];
                ah[0] = splitf16(s0[0], s0[1], al[0]);
                ah[1] = splitf16(s0[2], s0[3], al[1]);
                ah[2] = splitf16(s1[0], s1[1], al[2]);
                ah[3] = splitf16(s1[2], s1[3], al[3]);
#pragma unroll
                for (int ndp = 0; ndp < 4; ndp++) {
                    uint32_t vb = (uint32_t)((ks2 * 16 + arow) * 144 + ndp * 32 + acolb);
                    uint32_t vh[4];
                    LDM_X4T(vh, vB + vb);
                    mma_f16(oa[2 * ndp], ah, &vh[0]);
                    mma_f16(oa[2 * ndp], al, &vh[0]);
                    mma_f16(oa[2 * ndp + 1], ah, &vh[2]);
                    mma_f16(oa[2 * ndp + 1], al, &vh[2]);
                }
            }
        } else {
            // far tile: 1-term S V
#pragma unroll
            for (int ks2 = 0; ks2 < 4; ks2++) {
                float* s0 = sreg[2 * ks2];
                float* s1 = sreg[2 * ks2 + 1];
                uint32_t ah[4];
                ah[0] = packf16(s0[0], s0[1]);
                ah[1] = packf16(s0[2], s0[3]);
                ah[2] = packf16(s1[0], s1[1]);
                ah[3] = packf16(s1[2], s1[3]);
#pragma unroll
                for (int ndp = 0; ndp < 4; ndp++) {
                    uint32_t vb = (uint32_t)((ks2 * 16 + arow) * 144 + ndp * 32 + acolb);
                    uint32_t vh[4];
                    LDM_X4T(vh, vB + vb);
                    mma_f16(oa[2 * ndp], ah, &vh[0]);
                    mma_f16(oa[2 * ndp + 1], ah, &vh[2]);
                }
            }
        }
    }

    // ---- combine half0 + half1 partials via smem (reuse K region) ----
    __syncthreads();   // all tile reads of K/V done
    float* red = (float*)(sm + A_K) + rg * REDSTR;
    if (half == 1) {
#pragma unroll
        for (int nd = 0; nd < 8; nd++) {
            int c = nd * 8 + 2 * tc;
            red[g * 68 + c] = oa[nd][0];
            red[g * 68 + c + 1] = oa[nd][1];
            red[(g + 8) * 68 + c] = oa[nd][2];
            red[(g + 8) * 68 + c + 1] = oa[nd][3];
        }
    }
    __syncthreads();
    if (half == 0) {
#pragma unroll
        for (int nd = 0; nd < 8; nd++) {
            int c = nd * 8 + 2 * tc;
            oa[nd][0] += red[g * 68 + c];
            oa[nd][1] += red[g * 68 + c + 1];
            oa[nd][2] += red[(g + 8) * 68 + c];
            oa[nd][3] += red[(g + 8) * 68 + c + 1];
        }
        int r0 = qsub * 64 + wq * 16 + g;
#pragma unroll
        for (int nd = 0; nd < 8; nd++) {
            int c = nd * 8 + 2 * tc;
            *(float2*)&out[(size_t)(gb + r0) * HD + c] = make_float2(oa[nd][0], oa[nd][1]);
            *(float2*)&out[(size_t)(gb + r0 + 8) * HD + c] = make_float2(oa[nd][2], oa[nd][3]);
        }
    }
}

// ---------------- launch ----------------
extern "C" void kernel_launch(void* const* d_in, const int* in_sizes, int n_in,
                              void* d_out, int out_size) {
    const float* X  = (const float*)d_in[0];
    const float* WQ = (const float*)d_in[1];
    const float* WK = (const float*)d_in[2];
    const float* WV = (const float*)d_in[3];
    float* out = (float*)d_out;

    prep_kernel<<<384, 256>>>(WQ, WK, WV);

    cudaFuncSetAttribute(proj_kernel, cudaFuncAttributeMaxDynamicSharedMemorySize, P_TOTAL);
    proj_kernel<<<256, 256, P_TOTAL>>>(X);

    cudaFuncSetAttribute(state_kernel, cudaFuncAttributeMaxDynamicSharedMemorySize, SC_TOTAL);
    state_kernel<<<dim3(7, B), 128, SC_TOTAL>>>();

    cudaFuncSetAttribute(attn_kernel, cudaFuncAttributeMaxDynamicSharedMemorySize, A_TOTAL);
    attn_kernel<<<dim3(16, B), 512, A_TOTAL>>>(out);
}

// round 16
// speedup vs baseline: 1.3712x; 1.0065x over previous
#include <cuda_runtime.h>
#include <cuda_bf16.h>
#include <cuda_fp16.h>
#include <math.h>
#include <stdint.h>

#define B 8
#define SEQ 2048
#define HID 512
#define HD 64
#define LGAM -0.04580369f   // log2(0.96875)

// ---------------- scratch (device globals; no allocation allowed) ----------------
__device__ __align__(256) uint16_t gQf[B * SEQ * HD];   // fp16 single
__device__ __align__(256) uint16_t gKf[B * SEQ * HD];   // fp16 single
__device__ __align__(256) uint16_t gVf[B * SEQ * HD];   // fp16 single
__device__ __align__(256) uint16_t gWf[192 * HID];      // fp16 W, [region*64+d][k]
__device__ __align__(256) float gC[B * 8 * HD * HD];    // chunk KV states, fp32
__device__ float tQc[SEQ * 32], tQs[SEQ * 32], tKc[SEQ * 32], tKs[SEQ * 32];

// ---------------- helpers ----------------
__device__ __forceinline__ void mma_f16(float* d, const uint32_t* a, const uint32_t* b) {
    asm volatile(
        "mma.sync.aligned.m16n8k16.row.col.f32.f16.f16.f32 "
        "{%0,%1,%2,%3}, {%4,%5,%6,%7}, {%8,%9}, {%0,%1,%2,%3};"
        : "+f"(d[0]), "+f"(d[1]), "+f"(d[2]), "+f"(d[3])
        : "r"(a[0]), "r"(a[1]), "r"(a[2]), "r"(a[3]), "r"(b[0]), "r"(b[1]));
}
#define LDM_X4(R, a) \
    asm volatile("ldmatrix.sync.aligned.m8n8.x4.shared.b16 {%0,%1,%2,%3}, [%4];" \
                 : "=r"((R)[0]), "=r"((R)[1]), "=r"((R)[2]), "=r"((R)[3]) : "r"(a))
#define LDM_X4T(R, a) \
    asm volatile("ldmatrix.sync.aligned.m8n8.x4.trans.shared.b16 {%0,%1,%2,%3}, [%4];" \
                 : "=r"((R)[0]), "=r"((R)[1]), "=r"((R)[2]), "=r"((R)[3]) : "r"(a))
#define CPA16(dst, src) \
    asm volatile("cp.async.ca.shared.global [%0], [%1], 16;" \
                 :: "r"(dst), "l"(__cvta_generic_to_global(src)))
#define CPA_COMMIT() asm volatile("cp.async.commit_group;")
#define CPA_WAIT0() asm volatile("cp.async.wait_group 0;")
__device__ __forceinline__ uint32_t smem_u32(const void* p) {
    uint32_t a;
    asm("{ .reg .u64 t; cvta.to.shared.u64 t, %1; cvt.u32.u64 %0, t; }" : "=r"(a) : "l"(p));
    return a;
}
__device__ __forceinline__ uint32_t packf16(float x0, float x1) {
    __half2 h = __floats2half2_rn(x0, x1);
    return *reinterpret_cast<uint32_t*>(&h);
}
__device__ __forceinline__ uint32_t splitf16(float x0, float x1, uint32_t& lo) {
    __half2 h = __floats2half2_rn(x0, x1);
    float2 hf = __half22float2(h);
    __half2 l = __floats2half2_rn(x0 - hf.x, x1 - hf.y);
    lo = *reinterpret_cast<uint32_t*>(&l);
    return *reinterpret_cast<uint32_t*>(&h);
}

// ---------------- kernel 0: xPos tables (fast-math) + W fp16 (coalesced) ----------------
__global__ void prep_kernel(const float* __restrict__ WQ,
                            const float* __restrict__ WK,
                            const float* __restrict__ WV) {
    int idx = blockIdx.x * blockDim.x + threadIdx.x;
    if (idx < SEQ * 32) {
        int t = idx >> 5;
        int m = idx & 31;
        float sv = (2.0f * (float)m + 0.4f * (float)HD) / (1.4f * (float)HD);
        float p = ((float)t * (1.0f / 512.0f)) * log2f(sv);
        float s = exp2f(p);
        float rs = exp2f(-p);
        float invf = exp2f(-(float)m * 0.41524101f);
        float sn, cs;
        __sincosf((float)t * invf, &sn, &cs);
        tQc[idx] = cs * s;
        tQs[idx] = sn * s;
        tKc[idx] = cs * rs;
        tKs[idx] = sn * rs;
    }
    if (idx < 3 * HID * HD) {
        int region = idx >> 15;
        int d = (idx >> 9) & 63;
        int k = idx & 511;
        const float* W = (region == 0) ? WQ : ((region == 1) ? WK : WV);
        __half hw = __float2half_rn(W[k * HD + d]);
        gWf[(region * 64 + d) * HID + k] = *reinterpret_cast<uint16_t*>(&hw);
    }
}

// ---------------- kernel 1: QKV projection, fp16 1-term HMMA + xPos ----------------
// 256 CTAs x 256 thr (8 warps 2x4). CTA tile 64x192, warp tile 32x48.
// W + A double-buffered; ONE barrier per chunk; W prefetch issued AFTER the
// barrier so it cannot race the previous chunk's reads of the same buffer.
#define PSTR 72
#define P_WB(s) ((s) * 27648)           // fp16 W stage, 192 x 64 (144B stride)
#define P_A(s)  (55296 + (s) * 9216)    // fp16 X tile, 64 x 64 (144B stride)
#define P_TOTAL 73728

__global__ __launch_bounds__(256, 2) void proj_kernel(const float* __restrict__ X) {
    extern __shared__ char sm[];
    uint32_t smb = smem_u32(sm);

    int tid = threadIdx.x;
    int wid = tid >> 5, lane = tid & 31;
    int wm = wid >> 2, wn = wid & 3;
    int g = lane >> 2, tc = lane & 3;

    int arow = lane & 15;
    int acolb = (lane >> 4) * 16;
    int krow = (lane & 7) + ((lane >> 4) << 3);
    int kcolb = ((lane >> 3) & 1) * 16;

    const float* Xb = X + (size_t)blockIdx.x * 64 * HID;

    float acc[2][6][4];
#pragma unroll
    for (int mt = 0; mt < 2; mt++)
#pragma unroll
        for (int nt = 0; nt < 6; nt++)
#pragma unroll
            for (int i = 0; i < 4; i++) acc[mt][nt][i] = 0.0f;

    float4 xr[4];
#pragma unroll
    for (int it = 0; it < 4; it++) {
        int e = tid + it * 256;
        int r = e >> 4, c = e & 15;
        xr[it] = *(const float4*)&Xb[r * HID + c * 4];
    }
#pragma unroll
    for (int it = 0; it < 6; it++) {
        int e = tid + it * 256;
        int r = e >> 3, c = e & 7;
        CPA16(smb + P_WB(0) + r * 144 + c * 16, &gWf[r * HID + c * 8]);
    }
    CPA_COMMIT();

    for (int chunk = 0; chunk < 8; chunk++) {
        int s = chunk & 1;
        int k0n = (chunk + 1) * 64;
        // convert register X -> A[s]
        {
            uint16_t* Ah = (uint16_t*)(sm + P_A(s));
#pragma unroll
            for (int it = 0; it < 4; it++) {
                int e = tid + it * 256;
                int r = e >> 4, c = e & 15;
                float4 v = xr[it];
                *(uint2*)&Ah[r * PSTR + 4 * c] =
                    make_uint2(packf16(v.x, v.y), packf16(v.z, v.w));
            }
        }
        // issue X loads for next chunk
        if (chunk < 7) {
#pragma unroll
            for (int it = 0; it < 4; it++) {
                int e = tid + it * 256;
                int r = e >> 4, c = e & 15;
                xr[it] = *(const float4*)&Xb[r * HID + k0n + c * 4];
            }
        }
        CPA_WAIT0();       // W[s] landed (committed at chunk-1)
        __syncthreads();   // single barrier: separates prev-chunk reads from new writes

        // NOW safe to prefetch W for next chunk into W[s^1]
        if (chunk < 7) {
#pragma unroll
            for (int it = 0; it < 6; it++) {
                int e = tid + it * 256;
                int r = e >> 3, c = e & 7;
                CPA16(smb + P_WB(s ^ 1) + r * 144 + c * 16, &gWf[r * HID + k0n + c * 8]);
            }
            CPA_COMMIT();
        }

        uint32_t wbase = smb + P_WB(s);
        uint32_t abase = smb + P_A(s);
#pragma unroll
        for (int ks = 0; ks < 4; ks++) {
            uint32_t ah[2][4];
#pragma unroll
            for (int mt = 0; mt < 2; mt++) {
                uint32_t rb = (uint32_t)((wm * 32 + mt * 16 + arow) * (PSTR * 2) + ks * 32 + acolb);
                LDM_X4(ah[mt], abase + rb);
            }
#pragma unroll
            for (int np = 0; np < 3; np++) {
                int n = wn * 48 + np * 16;
                uint32_t bb = (uint32_t)((n + krow) * (PSTR * 2) + ks * 32 + kcolb);
                uint32_t bf[4];
                LDM_X4(bf, wbase + bb);
#pragma unroll
                for (int mt = 0; mt < 2; mt++) {
                    mma_f16(acc[mt][2 * np], ah[mt], &bf[0]);
                    mma_f16(acc[mt][2 * np + 1], ah[mt], &bf[2]);
                }
            }
        }
    }

    // epilogue: rotary, store Q/K/V fp16 single
#pragma unroll
    for (int mt = 0; mt < 2; mt++) {
#pragma unroll
        for (int half = 0; half < 2; half++) {
            int lrow = wm * 32 + mt * 16 + g + half * 8;
            int grow = blockIdx.x * 64 + lrow;
            int tpos = grow & (SEQ - 1);
#pragma unroll
            for (int nt = 0; nt < 6; nt++) {
                int c = wn * 48 + nt * 8 + 2 * tc;
                float v0 = acc[mt][nt][half * 2];
                float v1 = acc[mt][nt][half * 2 + 1];
                if (c < 64) {
                    int m = c >> 1;
                    float cs = tQc[tpos * 32 + m], sn = tQs[tpos * 32 + m];
                    ((uint32_t*)gQf)[grow * 32 + m] = packf16(v0 * cs - v1 * sn, v1 * cs + v0 * sn);
                } else if (c < 128) {
                    int m = (c - 64) >> 1;
                    float cs = tKc[tpos * 32 + m], sn = tKs[tpos * 32 + m];
                    ((uint32_t*)gKf)[grow * 32 + m] = packf16(v0 * cs - v1 * sn, v1 * cs + v0 * sn);
                } else {
                    int m = (c - 128) >> 1;
                    ((uint32_t*)gVf)[grow * 32 + m] = packf16(v0, v1);
                }
            }
        }
    }
}

// ---------------- kernel 1.5: chunk KV state C_c (fp16 1-term) ----------------
#define SC_K 0
#define SC_V 9216
#define SC_TOTAL 18432

__global__ __launch_bounds__(128) void state_kernel() {
    extern __shared__ char sm[];
    uint32_t smb = smem_u32(sm);
    int c = blockIdx.x, b = blockIdx.y;
    int tid = threadIdx.x;
    int wid = tid >> 5, lane = tid & 31;
    int g = lane >> 2, tc = lane & 3;

    int arow = lane & 15;
    int acolb = (lane >> 4) * 16;
    int krow = (lane & 7) + ((lane >> 4) << 3);
    int kcolb = ((lane >> 3) & 1) * 16;

    float acc[8][4];
#pragma unroll
    for (int nd = 0; nd < 8; nd++)
#pragma unroll
        for (int i = 0; i < 4; i++) acc[nd][i] = 0.0f;

    for (int jt = 0; jt < 4; jt++) {
        __syncthreads();
        int jb = b * SEQ + c * 256 + jt * 64;
#pragma unroll
        for (int it = 0; it < 4; it++) {
            int e = tid + it * 128;
            int r = e >> 3, cc = e & 7;
            *(float4*)(sm + SC_K + r * 144 + cc * 16) = *(const float4*)&gKf[(size_t)(jb + r) * HD + cc * 8];
        }
#pragma unroll
        for (int it = 0; it < 16; it++) {
            int p = tid + it * 128;
            int r = p >> 5, vp = p & 31;
            uint32_t u = ((const uint32_t*)gVf)[(size_t)(jb + r) * 32 + vp];
            __half2 hv = *reinterpret_cast<__half2*>(&u);
            float2 f = __half22float2(hv);
            float w = exp2f(LGAM * (float)(256 - (jt * 64 + r)));
            *(uint32_t*)(sm + SC_V + r * 144 + vp * 4) = packf16(w * f.x, w * f.y);
        }
        __syncthreads();

#pragma unroll
        for (int ks = 0; ks < 4; ks++) {
            uint32_t ab = (uint32_t)((ks * 16 + krow) * 144 + wid * 32 + kcolb);
            uint32_t ah[4];
            LDM_X4T(ah, smb + SC_K + ab);
#pragma unroll
            for (int ndp = 0; ndp < 4; ndp++) {
                uint32_t vb = (uint32_t)((ks * 16 + arow) * 144 + ndp * 32 + acolb);
                uint32_t vh[4];
                LDM_X4T(vh, smb + SC_V + vb);
                mma_f16(acc[2 * ndp], ah, &vh[0]);
                mma_f16(acc[2 * ndp + 1], ah, &vh[2]);
            }
        }
    }

    float* Cb = gC + ((size_t)(b * 8 + c)) * 4096;
#pragma unroll
    for (int nd = 0; nd < 8; nd++) {
        int v = nd * 8 + 2 * tc;
        int d0 = wid * 16 + g;
        *(float2*)&Cb[d0 * 64 + v] = make_float2(acc[nd][0], acc[nd][1]);
        *(float2*)&Cb[(d0 + 8) * 64 + v] = make_float2(acc[nd][2], acc[nd][3]);
    }
}

// ---------------- kernel 2: retention attention (16 warps, k-split pairs, Q fp16) ----------------
// grid (16, 8) x 512 thr. rg = wid>>1 (16 q-rows), half = wid&1.
// State-apply split across halves (half h does output col-groups 2h, 2h+1);
// half0: tiles {0,1}, half1: tiles {2,3}; partials summed via smem.
#define A_Q 0             // 128 x 144B
#define A_MH 18432        // 64 x 144B
#define A_ML 27648
#define A_K 36864         // 256 x 144B
#define A_V 73728
#define A_DEC 110592      // 511 floats
#define A_TOTAL 112640
#define REDSTR 1088       // reduction block stride (floats)

__global__ __launch_bounds__(512, 1) void attn_kernel(float* __restrict__ out) {
    extern __shared__ char sm[];
    uint16_t* Qs = (uint16_t*)(sm + A_Q);
    float* sDec = (float*)(sm + A_DEC);
    uint32_t smb = smem_u32(sm);

    int qtp = blockIdx.x, b = blockIdx.y;
    int tid = threadIdx.x;
    int wid = tid >> 5, lane = tid & 31;
    int rg = wid >> 1, half = wid & 1;
    int qsub = rg >> 2, wq = rg & 3;
    int g = lane >> 2, tc = lane & 3;
    int q0 = qtp * 128;
    int gb = b * SEQ + q0;
    int chunk = qtp >> 1;
    int qt_w = qtp * 2 + qsub;

    int arow = lane & 15;
    int acolb = (lane >> 4) * 16;
    int krow = (lane & 7) + ((lane >> 4) << 3);
    int kcolb = ((lane >> 3) & 1) * 16;

    // ---- stage ALL 4 K/V tiles (whole chunk, 256 rows) ----
    {
        int kb0 = b * SEQ + chunk * 256;
#pragma unroll
        for (int it = 0; it < 4; it++) {
            int e = tid + it * 512;
            int r = e >> 3, c = e & 7;
            uint32_t off = (uint32_t)(r * 144 + c * 16);
            CPA16(smb + A_K + off, &gKf[(size_t)(kb0 + r) * HD + c * 8]);
            CPA16(smb + A_V + off, &gVf[(size_t)(kb0 + r) * HD + c * 8]);
        }
        CPA_COMMIT();
    }

    // Q (128 rows fp16), decay window, state M
#pragma unroll
    for (int it = 0; it < 2; it++) {
        int e = tid + it * 512;
        int r = e >> 3, c = e & 7;
        *(float4*)&Qs[r * 72 + c * 8] = *(const float4*)&gQf[(size_t)(gb + r) * HD + c * 8];
    }
    if (tid < 511) sDec[tid] = exp2f(LGAM * fabsf((float)(tid - 255)));
    if (chunk >= 1) {
        const float2* C1 = (const float2*)(gC + ((size_t)(b * 8 + chunk - 1)) * 4096);
        const float2* C2 = (chunk >= 2) ? (const float2*)(gC + ((size_t)(b * 8 + chunk - 2)) * 4096) : (const float2*)0;
        const float G256 = 2.952517e-4f;   // gamma^256
#pragma unroll
        for (int it = 0; it < 4; it++) {
            int p = tid + it * 512;
            int d = p >> 5, vp = p & 31;
            float2 v = C1[p];
            if (C2) {
                float2 w = C2[p];
                v.x += G256 * w.x;
                v.y += G256 * w.y;
            }
            uint32_t lo;
            uint32_t hi = splitf16(v.x, v.y, lo);
            *(uint32_t*)(sm + A_MH + d * 144 + vp * 4) = hi;
            *(uint32_t*)(sm + A_ML + d * 144 + vp * 4) = lo;
        }
    }
    __syncthreads();

    // Q fragments (both halves load the same rows)
    uint32_t qh[4][4];
#pragma unroll
    for (int ks = 0; ks < 4; ks++) {
        uint32_t rb = (uint32_t)((qsub * 64 + wq * 16 + arow) * 144 + ks * 32 + acolb);
        LDM_X4(qh[ks], smb + A_Q + rb);
    }

    float oa[8][4];
#pragma unroll
    for (int nd = 0; nd < 8; nd++)
#pragma unroll
        for (int i = 0; i < 4; i++) oa[nd][i] = 0.0f;

    int i0 = q0 + qsub * 64 + wq * 16 + g;

    // ---- state apply, SPLIT across halves: half h owns ndp = 2h, 2h+1 ----
    if (chunk >= 1) {
        float T[4][4];
#pragma unroll
        for (int nd = 0; nd < 4; nd++)
#pragma unroll
            for (int i = 0; i < 4; i++) T[nd][i] = 0.0f;
#pragma unroll
        for (int ks = 0; ks < 4; ks++) {
#pragma unroll
            for (int nn = 0; nn < 2; nn++) {
                int ndp = half * 2 + nn;
                uint32_t vb = (uint32_t)((ks * 16 + arow) * 144 + ndp * 32 + acolb);
                uint32_t mh[4], ml[4];
                LDM_X4T(mh, smb + A_MH + vb);
                LDM_X4T(ml, smb + A_ML + vb);
                mma_f16(T[2 * nn], qh[ks], &mh[0]);
                mma_f16(T[2 * nn], qh[ks], &ml[0]);
                mma_f16(T[2 * nn + 1], qh[ks], &mh[2]);
                mma_f16(T[2 * nn + 1], qh[ks], &ml[2]);
            }
        }
        int c0 = chunk * 256;
        float sc0 = sDec[i0 - c0 + 255];
        float sc1 = sDec[i0 + 8 - c0 + 255];
#pragma unroll
        for (int nn = 0; nn < 2; nn++) {
            int ndp = half * 2 + nn;
            oa[2 * ndp][0] += sc0 * T[2 * nn][0];
            oa[2 * ndp][1] += sc0 * T[2 * nn][1];
            oa[2 * ndp][2] += sc1 * T[2 * nn][2];
            oa[2 * ndp][3] += sc1 * T[2 * nn][3];
            oa[2 * ndp + 1][0] += sc0 * T[2 * nn + 1][0];
            oa[2 * ndp + 1][1] += sc0 * T[2 * nn + 1][1];
            oa[2 * ndp + 1][2] += sc1 * T[2 * nn + 1][2];
            oa[2 * ndp + 1][3] += sc1 * T[2 * nn + 1][3];
        }
    }

    CPA_WAIT0();
    __syncthreads();

    // ---- 2 intra-chunk tiles per half warp ----
#pragma unroll
    for (int ii = 0; ii < 2; ii++) {
        int i = half * 2 + ii;
        int kt = chunk * 4 + i;
        int dd = qt_w - kt;
        bool nr = (dd <= 2) && (dd >= -2);
        uint32_t kB = smb + A_K + (uint32_t)(i * 64 * 144);
        uint32_t vB = smb + A_V + (uint32_t)(i * 64 * 144);

        float sreg[8][4];
#pragma unroll
        for (int nt = 0; nt < 8; nt++)
#pragma unroll
            for (int jj = 0; jj < 4; jj++) sreg[nt][jj] = 0.0f;

        // S = Q K^T (1-term, Q single fp16)
#pragma unroll
        for (int ks = 0; ks < 4; ks++) {
#pragma unroll
            for (int np = 0; np < 4; np++) {
                uint32_t bb = (uint32_t)((np * 16 + krow) * 144 + ks * 32 + kcolb);
                uint32_t kh[4];
                LDM_X4(kh, kB + bb);
                mma_f16(sreg[2 * np], qh[ks], &kh[0]);
                mma_f16(sreg[2 * np + 1], qh[ks], &kh[2]);
            }
        }
        // decay
#pragma unroll
        for (int nt = 0; nt < 8; nt++) {
            int base = i0 - (kt * 64 + nt * 8 + 2 * tc) + 255;
            sreg[nt][0] *= sDec[base];
            sreg[nt][1] *= sDec[base - 1];
            sreg[nt][2] *= sDec[base + 8];
            sreg[nt][3] *= sDec[base + 7];
        }

        if (nr) {
            // O += (Sh+Sl) V (2-term split, in-register)
#pragma unroll
            for (int ks2 = 0; ks2 < 4; ks2++) {
                float* s0 = sreg[2 * ks2];
                float* s1 = sreg[2 * ks2 + 1];
                uint32_t ah[4], al[4];
                ah[0] = splitf16(s0[0], s0[1], al[0]);
                ah[1] = splitf16(s0[2], s0[3], al[1]);
                ah[2] = splitf16(s1[0], s1[1], al[2]);
                ah[3] = splitf16(s1[2], s1[3], al[3]);
#pragma unroll
                for (int ndp = 0; ndp < 4; ndp++) {
                    uint32_t vb = (uint32_t)((ks2 * 16 + arow) * 144 + ndp * 32 + acolb);
                    uint32_t vh[4];
                    LDM_X4T(vh, vB + vb);
                    mma_f16(oa[2 * ndp], ah, &vh[0]);
                    mma_f16(oa[2 * ndp], al, &vh[0]);
                    mma_f16(oa[2 * ndp + 1], ah, &vh[2]);
                    mma_f16(oa[2 * ndp + 1], al, &vh[2]);
                }
            }
        } else {
            // far tile: 1-term S V
#pragma unroll
            for (int ks2 = 0; ks2 < 4; ks2++) {
                float* s0 = sreg[2 * ks2];
                float* s1 = sreg[2 * ks2 + 1];
                uint32_t ah[4];
                ah[0] = packf16(s0[0], s0[1]);
                ah[1] = packf16(s0[2], s0[3]);
                ah[2] = packf16(s1[0], s1[1]);
                ah[3] = packf16(s1[2], s1[3]);
#pragma unroll
                for (int ndp = 0; ndp < 4; ndp++) {
                    uint32_t vb = (uint32_t)((ks2 * 16 + arow) * 144 + ndp * 32 + acolb);
                    uint32_t vh[4];
                    LDM_X4T(vh, vB + vb);
                    mma_f16(oa[2 * ndp], ah, &vh[0]);
                    mma_f16(oa[2 * ndp + 1], ah, &vh[2]);
                }
            }
        }
    }

    // ---- combine half0 + half1 partials via smem (reuse K region) ----
    __syncthreads();   // all tile reads of K/V done
    float* red = (float*)(sm + A_K) + rg * REDSTR;
    if (half == 1) {
#pragma unroll
        for (int nd = 0; nd < 8; nd++) {
            int c = nd * 8 + 2 * tc;
            red[g * 68 + c] = oa[nd][0];
            red[g * 68 + c + 1] = oa[nd][1];
            red[(g + 8) * 68 + c] = oa[nd][2];
            red[(g + 8) * 68 + c + 1] = oa[nd][3];
        }
    }
    __syncthreads();
    if (half == 0) {
#pragma unroll
        for (int nd = 0; nd < 8; nd++) {
            int c = nd * 8 + 2 * tc;
            oa[nd][0] += red[g * 68 + c];
            oa[nd][1] += red[g * 68 + c + 1];
            oa[nd][2] += red[(g + 8) * 68 + c];
            oa[nd][3] += red[(g + 8) * 68 + c + 1];
        }
        int r0 = qsub * 64 + wq * 16 + g;
#pragma unroll
        for (int nd = 0; nd < 8; nd++) {
            int c = nd * 8 + 2 * tc;
            *(float2*)&out[(size_t)(gb + r0) * HD + c] = make_float2(oa[nd][0], oa[nd][1]);
            *(float2*)&out[(size_t)(gb + r0 + 8) * HD + c] = make_float2(oa[nd][2], oa[nd][3]);
        }
    }
}

// ---------------- launch ----------------
extern "C" void kernel_launch(void* const* d_in, const int* in_sizes, int n_in,
                              void* d_out, int out_size) {
    const float* X  = (const float*)d_in[0];
    const float* WQ = (const float*)d_in[1];
    const float* WK = (const float*)d_in[2];
    const float* WV = (const float*)d_in[3];
    float* out = (float*)d_out;

    prep_kernel<<<384, 256>>>(WQ, WK, WV);

    cudaFuncSetAttribute(proj_kernel, cudaFuncAttributeMaxDynamicSharedMemorySize, P_TOTAL);
    proj_kernel<<<256, 256, P_TOTAL>>>(X);

    cudaFuncSetAttribute(state_kernel, cudaFuncAttributeMaxDynamicSharedMemorySize, SC_TOTAL);
    state_kernel<<<dim3(7, B), 128, SC_TOTAL>>>();

    cudaFuncSetAttribute(attn_kernel, cudaFuncAttributeMaxDynamicSharedMemorySize, A_TOTAL);
    attn_kernel<<<dim3(16, B), 512, A_TOTAL>>>(out);
}

// round 17
// speedup vs baseline: 1.4452x; 1.0539x over previous
#include <cuda_runtime.h>
#include <cuda_bf16.h>
#include <cuda_fp16.h>
#include <math.h>
#include <stdint.h>

#define B 8
#define SEQ 2048
#define HID 512
#define HD 64
#define LGAM -0.04580369f   // log2(0.96875)

// ---------------- scratch (device globals; no allocation allowed) ----------------
__device__ __align__(256) uint16_t gQf[B * SEQ * HD];   // fp16 single
__device__ __align__(256) uint16_t gKf[B * SEQ * HD];   // fp16 single
__device__ __align__(256) uint16_t gVf[B * SEQ * HD];   // fp16 single
__device__ __align__(256) uint16_t gWf[192 * HID];      // fp16 W, [region*64+d][k]
__device__ __align__(256) float gC[B * 8 * HD * HD];    // chunk KV states, fp32
__device__ float tQc[SEQ * 32], tQs[SEQ * 32], tKc[SEQ * 32], tKs[SEQ * 32];

// ---------------- helpers ----------------
__device__ __forceinline__ void mma_f16(float* d, const uint32_t* a, const uint32_t* b) {
    asm volatile(
        "mma.sync.aligned.m16n8k16.row.col.f32.f16.f16.f32 "
        "{%0,%1,%2,%3}, {%4,%5,%6,%7}, {%8,%9}, {%0,%1,%2,%3};"
        : "+f"(d[0]), "+f"(d[1]), "+f"(d[2]), "+f"(d[3])
        : "r"(a[0]), "r"(a[1]), "r"(a[2]), "r"(a[3]), "r"(b[0]), "r"(b[1]));
}
#define LDM_X4(R, a) \
    asm volatile("ldmatrix.sync.aligned.m8n8.x4.shared.b16 {%0,%1,%2,%3}, [%4];" \
                 : "=r"((R)[0]), "=r"((R)[1]), "=r"((R)[2]), "=r"((R)[3]) : "r"(a))
#define LDM_X4T(R, a) \
    asm volatile("ldmatrix.sync.aligned.m8n8.x4.trans.shared.b16 {%0,%1,%2,%3}, [%4];" \
                 : "=r"((R)[0]), "=r"((R)[1]), "=r"((R)[2]), "=r"((R)[3]) : "r"(a))
#define CPA16(dst, src) \
    asm volatile("cp.async.ca.shared.global [%0], [%1], 16;" \
                 :: "r"(dst), "l"(__cvta_generic_to_global(src)))
#define CPA_COMMIT() asm volatile("cp.async.commit_group;")
#define CPA_WAIT0() asm volatile("cp.async.wait_group 0;")
__device__ __forceinline__ uint32_t smem_u32(const void* p) {
    uint32_t a;
    asm("{ .reg .u64 t; cvta.to.shared.u64 t, %1; cvt.u32.u64 %0, t; }" : "=r"(a) : "l"(p));
    return a;
}
__device__ __forceinline__ uint32_t packf16(float x0, float x1) {
    __half2 h = __floats2half2_rn(x0, x1);
    return *reinterpret_cast<uint32_t*>(&h);
}
__device__ __forceinline__ uint32_t splitf16(float x0, float x1, uint32_t& lo) {
    __half2 h = __floats2half2_rn(x0, x1);
    float2 hf = __half22float2(h);
    __half2 l = __floats2half2_rn(x0 - hf.x, x1 - hf.y);
    lo = *reinterpret_cast<uint32_t*>(&l);
    return *reinterpret_cast<uint32_t*>(&h);
}

// ---------------- kernel 0: xPos tables (fast-math) + W fp16 (coalesced) ----------------
__global__ void prep_kernel(const float* __restrict__ WQ,
                            const float* __restrict__ WK,
                            const float* __restrict__ WV) {
    int idx = blockIdx.x * blockDim.x + threadIdx.x;
    if (idx < SEQ * 32) {
        int t = idx >> 5;
        int m = idx & 31;
        float sv = (2.0f * (float)m + 0.4f * (float)HD) / (1.4f * (float)HD);
        float p = ((float)t * (1.0f / 512.0f)) * log2f(sv);
        float s = exp2f(p);
        float rs = exp2f(-p);
        float invf = exp2f(-(float)m * 0.41524101f);
        float sn, cs;
        __sincosf((float)t * invf, &sn, &cs);
        tQc[idx] = cs * s;
        tQs[idx] = sn * s;
        tKc[idx] = cs * rs;
        tKs[idx] = sn * rs;
    }
    if (idx < 3 * HID * HD) {
        int region = idx >> 15;
        int d = (idx >> 9) & 63;
        int k = idx & 511;
        const float* W = (region == 0) ? WQ : ((region == 1) ? WK : WV);
        __half hw = __float2half_rn(W[k * HD + d]);
        gWf[(region * 64 + d) * HID + k] = *reinterpret_cast<uint16_t*>(&hw);
    }
}

// ---------------- kernel 1: QKV projection, fp16 1-term HMMA + xPos ----------------
// 256 CTAs x 256 thr (8 warps 2x4). CTA tile 64x192, warp tile 32x48.
// W + A double-buffered; ONE barrier per chunk; W prefetch issued AFTER the
// barrier so it cannot race the previous chunk's reads of the same buffer.
#define PSTR 72
#define P_WB(s) ((s) * 27648)           // fp16 W stage, 192 x 64 (144B stride)
#define P_A(s)  (55296 + (s) * 9216)    // fp16 X tile, 64 x 64 (144B stride)
#define P_TOTAL 73728

__global__ __launch_bounds__(256, 2) void proj_kernel(const float* __restrict__ X) {
    extern __shared__ char sm[];
    uint32_t smb = smem_u32(sm);

    int tid = threadIdx.x;
    int wid = tid >> 5, lane = tid & 31;
    int wm = wid >> 2, wn = wid & 3;
    int g = lane >> 2, tc = lane & 3;

    int arow = lane & 15;
    int acolb = (lane >> 4) * 16;
    int krow = (lane & 7) + ((lane >> 4) << 3);
    int kcolb = ((lane >> 3) & 1) * 16;

    const float* Xb = X + (size_t)blockIdx.x * 64 * HID;

    float acc[2][6][4];
#pragma unroll
    for (int mt = 0; mt < 2; mt++)
#pragma unroll
        for (int nt = 0; nt < 6; nt++)
#pragma unroll
            for (int i = 0; i < 4; i++) acc[mt][nt][i] = 0.0f;

    float4 xr[4];
#pragma unroll
    for (int it = 0; it < 4; it++) {
        int e = tid + it * 256;
        int r = e >> 4, c = e & 15;
        xr[it] = *(const float4*)&Xb[r * HID + c * 4];
    }
#pragma unroll
    for (int it = 0; it < 6; it++) {
        int e = tid + it * 256;
        int r = e >> 3, c = e & 7;
        CPA16(smb + P_WB(0) + r * 144 + c * 16, &gWf[r * HID + c * 8]);
    }
    CPA_COMMIT();

    for (int chunk = 0; chunk < 8; chunk++) {
        int s = chunk & 1;
        int k0n = (chunk + 1) * 64;
        // convert register X -> A[s]
        {
            uint16_t* Ah = (uint16_t*)(sm + P_A(s));
#pragma unroll
            for (int it = 0; it < 4; it++) {
                int e = tid + it * 256;
                int r = e >> 4, c = e & 15;
                float4 v = xr[it];
                *(uint2*)&Ah[r * PSTR + 4 * c] =
                    make_uint2(packf16(v.x, v.y), packf16(v.z, v.w));
            }
        }
        // issue X loads for next chunk
        if (chunk < 7) {
#pragma unroll
            for (int it = 0; it < 4; it++) {
                int e = tid + it * 256;
                int r = e >> 4, c = e & 15;
                xr[it] = *(const float4*)&Xb[r * HID + k0n + c * 4];
            }
        }
        CPA_WAIT0();       // W[s] landed (committed previous chunk)
        __syncthreads();   // single barrier: separates prev-chunk reads from new writes

        // safe to prefetch next W into W[s^1] now
        if (chunk < 7) {
#pragma unroll
            for (int it = 0; it < 6; it++) {
                int e = tid + it * 256;
                int r = e >> 3, c = e & 7;
                CPA16(smb + P_WB(s ^ 1) + r * 144 + c * 16, &gWf[r * HID + k0n + c * 8]);
            }
            CPA_COMMIT();
        }

        uint32_t wbase = smb + P_WB(s);
        uint32_t abase = smb + P_A(s);
#pragma unroll
        for (int ks = 0; ks < 4; ks++) {
            uint32_t ah[2][4];
#pragma unroll
            for (int mt = 0; mt < 2; mt++) {
                uint32_t rb = (uint32_t)((wm * 32 + mt * 16 + arow) * (PSTR * 2) + ks * 32 + acolb);
                LDM_X4(ah[mt], abase + rb);
            }
#pragma unroll
            for (int np = 0; np < 3; np++) {
                int n = wn * 48 + np * 16;
                uint32_t bb = (uint32_t)((n + krow) * (PSTR * 2) + ks * 32 + kcolb);
                uint32_t bf[4];
                LDM_X4(bf, wbase + bb);
#pragma unroll
                for (int mt = 0; mt < 2; mt++) {
                    mma_f16(acc[mt][2 * np], ah[mt], &bf[0]);
                    mma_f16(acc[mt][2 * np + 1], ah[mt], &bf[2]);
                }
            }
        }
    }

    // epilogue: rotary, store Q/K/V fp16 single
#pragma unroll
    for (int mt = 0; mt < 2; mt++) {
#pragma unroll
        for (int half = 0; half < 2; half++) {
            int lrow = wm * 32 + mt * 16 + g + half * 8;
            int grow = blockIdx.x * 64 + lrow;
            int tpos = grow & (SEQ - 1);
#pragma unroll
            for (int nt = 0; nt < 6; nt++) {
                int c = wn * 48 + nt * 8 + 2 * tc;
                float v0 = acc[mt][nt][half * 2];
                float v1 = acc[mt][nt][half * 2 + 1];
                if (c < 64) {
                    int m = c >> 1;
                    float cs = tQc[tpos * 32 + m], sn = tQs[tpos * 32 + m];
                    ((uint32_t*)gQf)[grow * 32 + m] = packf16(v0 * cs - v1 * sn, v1 * cs + v0 * sn);
                } else if (c < 128) {
                    int m = (c - 64) >> 1;
                    float cs = tKc[tpos * 32 + m], sn = tKs[tpos * 32 + m];
                    ((uint32_t*)gKf)[grow * 32 + m] = packf16(v0 * cs - v1 * sn, v1 * cs + v0 * sn);
                } else {
                    int m = (c - 128) >> 1;
                    ((uint32_t*)gVf)[grow * 32 + m] = packf16(v0, v1);
                }
            }
        }
    }
}

// ---------------- kernel 1.5: chunk KV state C_c (fp16 1-term) ----------------
#define SC_K 0
#define SC_V 9216
#define SC_TOTAL 18432

__global__ __launch_bounds__(128) void state_kernel() {
    extern __shared__ char sm[];
    uint32_t smb = smem_u32(sm);
    int c = blockIdx.x, b = blockIdx.y;
    int tid = threadIdx.x;
    int wid = tid >> 5, lane = tid & 31;
    int g = lane >> 2, tc = lane & 3;

    int arow = lane & 15;
    int acolb = (lane >> 4) * 16;
    int krow = (lane & 7) + ((lane >> 4) << 3);
    int kcolb = ((lane >> 3) & 1) * 16;

    float acc[8][4];
#pragma unroll
    for (int nd = 0; nd < 8; nd++)
#pragma unroll
        for (int i = 0; i < 4; i++) acc[nd][i] = 0.0f;

    for (int jt = 0; jt < 4; jt++) {
        __syncthreads();
        int jb = b * SEQ + c * 256 + jt * 64;
#pragma unroll
        for (int it = 0; it < 4; it++) {
            int e = tid + it * 128;
            int r = e >> 3, cc = e & 7;
            *(float4*)(sm + SC_K + r * 144 + cc * 16) = *(const float4*)&gKf[(size_t)(jb + r) * HD + cc * 8];
        }
#pragma unroll
        for (int it = 0; it < 16; it++) {
            int p = tid + it * 128;
            int r = p >> 5, vp = p & 31;
            uint32_t u = ((const uint32_t*)gVf)[(size_t)(jb + r) * 32 + vp];
            __half2 hv = *reinterpret_cast<__half2*>(&u);
            float2 f = __half22float2(hv);
            float w = exp2f(LGAM * (float)(256 - (jt * 64 + r)));
            *(uint32_t*)(sm + SC_V + r * 144 + vp * 4) = packf16(w * f.x, w * f.y);
        }
        __syncthreads();

#pragma unroll
        for (int ks = 0; ks < 4; ks++) {
            uint32_t ab = (uint32_t)((ks * 16 + krow) * 144 + wid * 32 + kcolb);
            uint32_t ah[4];
            LDM_X4T(ah, smb + SC_K + ab);
#pragma unroll
            for (int ndp = 0; ndp < 4; ndp++) {
                uint32_t vb = (uint32_t)((ks * 16 + arow) * 144 + ndp * 32 + acolb);
                uint32_t vh[4];
                LDM_X4T(vh, smb + SC_V + vb);
                mma_f16(acc[2 * ndp], ah, &vh[0]);
                mma_f16(acc[2 * ndp + 1], ah, &vh[2]);
            }
        }
    }

    float* Cb = gC + ((size_t)(b * 8 + c)) * 4096;
#pragma unroll
    for (int nd = 0; nd < 8; nd++) {
        int v = nd * 8 + 2 * tc;
        int d0 = wid * 16 + g;
        *(float2*)&Cb[d0 * 64 + v] = make_float2(acc[nd][0], acc[nd][1]);
        *(float2*)&Cb[(d0 + 8) * 64 + v] = make_float2(acc[nd][2], acc[nd][3]);
    }
}

// ---------------- kernel 2: retention attention (16 warps, k-split pairs, Q fp16) ----------------
// grid (16, 8) x 512 thr. rg = wid>>1 (16 q-rows), half = wid&1.
// State-apply on half0 ONLY (asymmetric schedule: half1 proceeds to tiles);
// half0: tiles {0,1}, half1: tiles {2,3}; partials summed via smem.
#define A_Q 0             // 128 x 144B
#define A_MH 18432        // 64 x 144B
#define A_ML 27648
#define A_K 36864         // 256 x 144B
#define A_V 73728
#define A_DEC 110592      // 511 floats
#define A_TOTAL 112640
#define REDSTR 1088       // reduction block stride (floats)

__global__ __launch_bounds__(512, 1) void attn_kernel(float* __restrict__ out) {
    extern __shared__ char sm[];
    uint16_t* Qs = (uint16_t*)(sm + A_Q);
    float* sDec = (float*)(sm + A_DEC);
    uint32_t smb = smem_u32(sm);

    int qtp = blockIdx.x, b = blockIdx.y;
    int tid = threadIdx.x;
    int wid = tid >> 5, lane = tid & 31;
    int rg = wid >> 1, half = wid & 1;
    int qsub = rg >> 2, wq = rg & 3;
    int g = lane >> 2, tc = lane & 3;
    int q0 = qtp * 128;
    int gb = b * SEQ + q0;
    int chunk = qtp >> 1;
    int qt_w = qtp * 2 + qsub;

    int arow = lane & 15;
    int acolb = (lane >> 4) * 16;
    int krow = (lane & 7) + ((lane >> 4) << 3);
    int kcolb = ((lane >> 3) & 1) * 16;

    // ---- stage ALL 4 K/V tiles (whole chunk, 256 rows) ----
    {
        int kb0 = b * SEQ + chunk * 256;
#pragma unroll
        for (int it = 0; it < 4; it++) {
            int e = tid + it * 512;
            int r = e >> 3, c = e & 7;
            uint32_t off = (uint32_t)(r * 144 + c * 16);
            CPA16(smb + A_K + off, &gKf[(size_t)(kb0 + r) * HD + c * 8]);
            CPA16(smb + A_V + off, &gVf[(size_t)(kb0 + r) * HD + c * 8]);
        }
        CPA_COMMIT();
    }

    // Q (128 rows fp16), decay window, state M
#pragma unroll
    for (int it = 0; it < 2; it++) {
        int e = tid + it * 512;
        int r = e >> 3, c = e & 7;
        *(float4*)&Qs[r * 72 + c * 8] = *(const float4*)&gQf[(size_t)(gb + r) * HD + c * 8];
    }
    if (tid < 511) sDec[tid] = exp2f(LGAM * fabsf((float)(tid - 255)));
    if (chunk >= 1) {
        const float2* C1 = (const float2*)(gC + ((size_t)(b * 8 + chunk - 1)) * 4096);
        const float2* C2 = (chunk >= 2) ? (const float2*)(gC + ((size_t)(b * 8 + chunk - 2)) * 4096) : (const float2*)0;
        const float G256 = 2.952517e-4f;   // gamma^256
#pragma unroll
        for (int it = 0; it < 4; it++) {
            int p = tid + it * 512;
            int d = p >> 5, vp = p & 31;
            float2 v = C1[p];
            if (C2) {
                float2 w = C2[p];
                v.x += G256 * w.x;
                v.y += G256 * w.y;
            }
            uint32_t lo;
            uint32_t hi = splitf16(v.x, v.y, lo);
            *(uint32_t*)(sm + A_MH + d * 144 + vp * 4) = hi;
            *(uint32_t*)(sm + A_ML + d * 144 + vp * 4) = lo;
        }
    }
    __syncthreads();

    // Q fragments (both halves load the same rows)
    uint32_t qh[4][4];
#pragma unroll
    for (int ks = 0; ks < 4; ks++) {
        uint32_t rb = (uint32_t)((qsub * 64 + wq * 16 + arow) * 144 + ks * 32 + acolb);
        LDM_X4(qh[ks], smb + A_Q + rb);
    }

    float oa[8][4];
#pragma unroll
    for (int nd = 0; nd < 8; nd++)
#pragma unroll
        for (int i = 0; i < 4; i++) oa[nd][i] = 0.0f;

    int i0 = q0 + qsub * 64 + wq * 16 + g;

    // ---- state apply (half0 only): O += gamma^(i-c0) * Q @ (Mh+Ml) ----
    if (chunk >= 1 && half == 0) {
        float T[8][4];
#pragma unroll
        for (int nd = 0; nd < 8; nd++)
#pragma unroll
            for (int i = 0; i < 4; i++) T[nd][i] = 0.0f;
#pragma unroll
        for (int ks = 0; ks < 4; ks++) {
#pragma unroll
            for (int ndp = 0; ndp < 4; ndp++) {
                uint32_t vb = (uint32_t)((ks * 16 + arow) * 144 + ndp * 32 + acolb);
                uint32_t mh[4], ml[4];
                LDM_X4T(mh, smb + A_MH + vb);
                LDM_X4T(ml, smb + A_ML + vb);
                mma_f16(T[2 * ndp], qh[ks], &mh[0]);
                mma_f16(T[2 * ndp], qh[ks], &ml[0]);
                mma_f16(T[2 * ndp + 1], qh[ks], &mh[2]);
                mma_f16(T[2 * ndp + 1], qh[ks], &ml[2]);
            }
        }
        int c0 = chunk * 256;
        float sc0 = sDec[i0 - c0 + 255];
        float sc1 = sDec[i0 + 8 - c0 + 255];
#pragma unroll
        for (int nd = 0; nd < 8; nd++) {
            oa[nd][0] += sc0 * T[nd][0];
            oa[nd][1] += sc0 * T[nd][1];
            oa[nd][2] += sc1 * T[nd][2];
            oa[nd][3] += sc1 * T[nd][3];
        }
    }

    CPA_WAIT0();
    __syncthreads();

    // ---- 2 intra-chunk tiles per half warp ----
#pragma unroll
    for (int ii = 0; ii < 2; ii++) {
        int i = half * 2 + ii;
        int kt = chunk * 4 + i;
        int dd = qt_w - kt;
        bool nr = (dd <= 2) && (dd >= -2);
        uint32_t kB = smb + A_K + (uint32_t)(i * 64 * 144);
        uint32_t vB = smb + A_V + (uint32_t)(i * 64 * 144);

        float sreg[8][4];
#pragma unroll
        for (int nt = 0; nt < 8; nt++)
#pragma unroll
            for (int jj = 0; jj < 4; jj++) sreg[nt][jj] = 0.0f;

        // S = Q K^T (1-term, Q single fp16)
#pragma unroll
        for (int ks = 0; ks < 4; ks++) {
#pragma unroll
            for (int np = 0; np < 4; np++) {
                uint32_t bb = (uint32_t)((np * 16 + krow) * 144 + ks * 32 + kcolb);
                uint32_t kh[4];
                LDM_X4(kh, kB + bb);
                mma_f16(sreg[2 * np], qh[ks], &kh[0]);
                mma_f16(sreg[2 * np + 1], qh[ks], &kh[2]);
            }
        }
        // decay
#pragma unroll
        for (int nt = 0; nt < 8; nt++) {
            int base = i0 - (kt * 64 + nt * 8 + 2 * tc) + 255;
            sreg[nt][0] *= sDec[base];
            sreg[nt][1] *= sDec[base - 1];
            sreg[nt][2] *= sDec[base + 8];
            sreg[nt][3] *= sDec[base + 7];
        }

        if (nr) {
            // O += (Sh+Sl) V (2-term split, in-register)
#pragma unroll
            for (int ks2 = 0; ks2 < 4; ks2++) {
                float* s0 = sreg[2 * ks2];
                float* s1 = sreg[2 * ks2 + 1];
                uint32_t ah[4], al[4];
                ah[0] = splitf16(s0[0], s0[1], al[0]);
                ah[1] = splitf16(s0[2], s0[3], al[1]);
                ah[2] = splitf16(s1[0], s1[1], al[2]);
                ah[3] = splitf16(s1[2], s1[3], al[3]);
#pragma unroll
                for (int ndp = 0; ndp < 4; ndp++) {
                    uint32_t vb = (uint32_t)((ks2 * 16 + arow) * 144 + ndp * 32 + acolb);
                    uint32_t vh[4];
                    LDM_X4T(vh, vB + vb);
                    mma_f16(oa[2 * ndp], ah, &vh[0]);
                    mma_f16(oa[2 * ndp], al, &vh[0]);
                    mma_f16(oa[2 * ndp + 1], ah, &vh[2]);
                    mma_f16(oa[2 * ndp + 1], al, &vh[2]);
                }
            }
        } else {
            // far tile: 1-term S V
#pragma unroll
            for (int ks2 = 0; ks2 < 4; ks2++) {
                float* s0 = sreg[2 * ks2];
                float* s1 = sreg[2 * ks2 + 1];
                uint32_t ah[4];
                ah[0] = packf16(s0[0], s0[1]);
                ah[1] = packf16(s0[2], s0[3]);
                ah[2] = packf16(s1[0], s1[1]);
                ah[3] = packf16(s1[2], s1[3]);
#pragma unroll
                for (int ndp = 0; ndp < 4; ndp++) {
                    uint32_t vb = (uint32_t)((ks2 * 16 + arow) * 144 + ndp * 32 + acolb);
                    uint32_t vh[4];
                    LDM_X4T(vh, vB + vb);
                    mma_f16(oa[2 * ndp], ah, &vh[0]);
                    mma_f16(oa[2 * ndp + 1], ah, &vh[2]);
                }
            }
        }
    }

    // ---- combine half0 + half1 partials via smem (reuse K region) ----
    __syncthreads();   // all tile reads of K/V done
    float* red = (float*)(sm + A_K) + rg * REDSTR;
    if (half == 1) {
#pragma unroll
        for (int nd = 0; nd < 8; nd++) {
            int c = nd * 8 + 2 * tc;
            red[g * 68 + c] = oa[nd][0];
            red[g * 68 + c + 1] = oa[nd][1];
            red[(g + 8) * 68 + c] = oa[nd][2];
            red[(g + 8) * 68 + c + 1] = oa[nd][3];
        }
    }
    __syncthreads();
    if (half == 0) {
#pragma unroll
        for (int nd = 0; nd < 8; nd++) {
            int c = nd * 8 + 2 * tc;
            oa[nd][0] += red[g * 68 + c];
            oa[nd][1] += red[g * 68 + c + 1];
            oa[nd][2] += red[(g + 8) * 68 + c];
            oa[nd][3] += red[(g + 8) * 68 + c + 1];
        }
        int r0 = qsub * 64 + wq * 16 + g;
#pragma unroll
        for (int nd = 0; nd < 8; nd++) {
            int c = nd * 8 + 2 * tc;
            *(float2*)&out[(size_t)(gb + r0) * HD + c] = make_float2(oa[nd][0], oa[nd][1]);
            *(float2*)&out[(size_t)(gb + r0 + 8) * HD + c] = make_float2(oa[nd][2], oa[nd][3]);
        }
    }
}

// ---------------- launch ----------------
extern "C" void kernel_launch(void* const* d_in, const int* in_sizes, int n_in,
                              void* d_out, int out_size) {
    const float* X  = (const float*)d_in[0];
    const float* WQ = (const float*)d_in[1];
    const float* WK = (const float*)d_in[2];
    const float* WV = (const float*)d_in[3];
    float* out = (float*)d_out;

    prep_kernel<<<384, 256>>>(WQ, WK, WV);

    cudaFuncSetAttribute(proj_kernel, cudaFuncAttributeMaxDynamicSharedMemorySize, P_TOTAL);
    proj_kernel<<<256, 256, P_TOTAL>>>(X);

    cudaFuncSetAttribute(state_kernel, cudaFuncAttributeMaxDynamicSharedMemorySize, SC_TOTAL);
    state_kernel<<<dim3(7, B), 128, SC_TOTAL>>>();

    cudaFuncSetAttribute(attn_kernel, cudaFuncAttributeMaxDynamicSharedMemorySize, A_TOTAL);
    attn_kernel<<<dim3(16, B), 512, A_TOTAL>>>(out);
}